// round 13
// baseline (speedup 1.0000x reference)
#include <cuda_runtime.h>
#include <cuda_bf16.h>
#include <cuda_fp16.h>
#include <math.h>
#include <stdint.h>

#define BATCH   2
#define SEQ     2048
#define DMODEL  1024
#define NHEADS  16
#define HDIM    64
#define WIN     64
#define MTOT    (BATCH*SEQ)   // 4096
#define WSZ     (DMODEL*DMODEL)

// ---------------- scratch (static device globals) ----------------
__device__ __half g_x16[MTOT*DMODEL];          // x rounded to fp16
__device__ __half g_w16[4*WSZ];                // transposed [n][k], fp16
__device__ __half g_q16[MTOT*DMODEL];
__device__ __half g_k16[MTOT*DMODEL];
__device__ __half g_v16[MTOT*DMODEL];
__device__ __half g_a16[MTOT*DMODEL];          // attention out, fp16

// ---------------- PTX helpers (non-'a' features only) ----------------
__device__ __forceinline__ uint32_t smem_u32(const void* p) {
    uint32_t a;
    asm("{ .reg .u64 t; cvta.to.shared.u64 t, %1; cvt.u32.u64 %0, t; }" : "=r"(a) : "l"(p));
    return a;
}
__device__ __forceinline__ void cp_async16(uint32_t s, const void* g) {
    asm volatile("cp.async.cg.shared.global [%0], [%1], 16;" :: "r"(s), "l"(g));
}
__device__ __forceinline__ void cp_async16z(uint32_t s, const void* g, uint32_t srcsz) {
    asm volatile("cp.async.cg.shared.global [%0], [%1], 16, %2;" :: "r"(s), "l"(g), "r"(srcsz));
}
#define CP_COMMIT() asm volatile("cp.async.commit_group;" ::: "memory")
#define CP_WAIT(n)  asm volatile("cp.async.wait_group %0;" :: "n"(n) : "memory")

__device__ __forceinline__ void ldsm_x4(uint32_t* r, uint32_t a) {
    asm volatile("ldmatrix.sync.aligned.m8n8.x4.shared.b16 {%0,%1,%2,%3}, [%4];"
        : "=r"(r[0]), "=r"(r[1]), "=r"(r[2]), "=r"(r[3]) : "r"(a));
}
__device__ __forceinline__ void ldsm_x2t(uint32_t* r, uint32_t a) {
    asm volatile("ldmatrix.sync.aligned.m8n8.x2.trans.shared.b16 {%0,%1}, [%2];"
        : "=r"(r[0]), "=r"(r[1]) : "r"(a));
}
__device__ __forceinline__ void mma_f16(float* d, const uint32_t* a, const uint32_t* b) {
    asm volatile(
        "mma.sync.aligned.m16n8k16.row.col.f32.f16.f16.f32 "
        "{%0,%1,%2,%3}, {%4,%5,%6,%7}, {%8,%9}, {%0,%1,%2,%3};"
        : "+f"(d[0]), "+f"(d[1]), "+f"(d[2]), "+f"(d[3])
        : "r"(a[0]), "r"(a[1]), "r"(a[2]), "r"(a[3]), "r"(b[0]), "r"(b[1]));
}

__device__ __forceinline__ uint32_t pack_hf2(float x, float y) {
    __half2 h = __floats2half2_rn(x, y);
    return *(uint32_t*)&h;
}

// ============================================================
// Fused prep: blocks [0,4096) convert x -> fp16;
//             blocks [4096,8192) transpose W[k][n] -> Wt[n][k] fp16.
// ============================================================
__global__ __launch_bounds__(256) void prep_kernel(
    const float* __restrict__ x,
    const float* __restrict__ Wq, const float* __restrict__ Wk,
    const float* __restrict__ Wv, const float* __restrict__ Wo)
{
    __shared__ float tile[32][33];
    int bid = blockIdx.x;
    if (bid < MTOT) {
        size_t off = (size_t)bid * DMODEL + threadIdx.x * 4;
        float4 v = *(const float4*)(x + off);
        *(__half2*)(g_x16 + off)     = __floats2half2_rn(v.x, v.y);
        *(__half2*)(g_x16 + off + 2) = __floats2half2_rn(v.z, v.w);
    } else {
        int t = bid - MTOT;                 // 0..4095
        int z = t >> 10;                    // 0..3
        int tt = t & 1023;                  // 0..1023
        const float* W = (z == 0) ? Wq : (z == 1) ? Wk : (z == 2) ? Wv : Wo;
        __half* T = g_w16 + (size_t)z * WSZ;
        int kb = (tt >> 5) * 32, nb = (tt & 31) * 32;
        int tx = threadIdx.x & 31, ty = threadIdx.x >> 5;   // ty 0..7
#pragma unroll
        for (int i = 0; i < 4; i++)
            tile[ty + 8 * i][tx] = W[(size_t)(kb + ty + 8 * i) * DMODEL + nb + tx];
        __syncthreads();
#pragma unroll
        for (int i = 0; i < 4; i++) {
            T[(size_t)(nb + ty + 8 * i) * DMODEL + kb + tx] =
                __float2half_rn(tile[tx][ty + 8 * i]);
        }
    }
}

// ============================================================
// Single-pass fp16 HMMA GEMM: C = A16 @ W16^T + bias
// CTA tile 128x128, BK=32, 4 warps (2x2), warp tile 64x64.
// 4-stage cp.async, single barrier per chunk; 80 KB -> 2 CTAs/SM.
// Fragment redundancy: A 2x, B 2x (was A 4x / B 2x with 8 warps).
// ============================================================
#define BK       32
#define PITCHB   80                    // bytes per SMEM row (40 fp16)
#define MAT_B    (128*PITCHB)          // 10240 B per matrix tile
#define STAGE_B2 (2*MAT_B)             // 20480 B per stage
#define NSTAGE   4
#define GEMM_SMEM (NSTAGE*STAGE_B2)    // 81920 B
#define ROW32B   (32*PITCHB)

__global__ __launch_bounds__(128) void hmma_gemm_kernel(
    int mode, const float* __restrict__ b0, const float* __restrict__ b1,
    const float* __restrict__ b2, float* __restrict__ outp)
{
    extern __shared__ char sm[];
    const uint32_t sbase = smem_u32(sm);

    const int tid  = threadIdx.x;
    const int lane = tid & 31;
    const int wid  = tid >> 5;          // 0..3
    const int wm   = wid >> 1;          // 0..1
    const int wn   = wid & 1;           // 0..1
    const int m0   = blockIdx.y * 128;
    const int n0   = blockIdx.x * 128;
    const int z    = blockIdx.z;

    const __half *A, *B;
    const float* bias;
    if (mode == 0) {
        A = g_x16;
        B = g_w16 + (size_t)z * WSZ;
        bias = (z == 0) ? b0 : (z == 1) ? b1 : b2;
    } else {
        A = g_a16;
        B = g_w16 + 3ull * WSZ;
        bias = b0;
    }

    // 128 threads: rows 0..31 per iter, 4 iters cover 128 rows; seg = 16B quarter
    const int rowA = tid >> 2;          // 0..31
    const int seg  = tid & 3;
    const uint32_t s0 = (uint32_t)rowA * PITCHB + (uint32_t)seg * 16;
    const __half* pA = A + (size_t)(m0 + rowA) * DMODEL + seg * 8;
    const __half* pB = B + (size_t)(n0 + rowA) * DMODEL + seg * 8;

#define PREFETCH(stage, cc) do {                                               \
    const int _k0 = (cc) * BK;                                                 \
    const uint32_t _sb = sbase + (uint32_t)(stage) * STAGE_B2 + s0;            \
    _Pragma("unroll")                                                          \
    for (int _i = 0; _i < 4; _i++) {                                           \
        cp_async16(_sb + _i * ROW32B,         pA + (size_t)_i * 32 * DMODEL + _k0); \
        cp_async16(_sb + MAT_B + _i * ROW32B, pB + (size_t)_i * 32 * DMODEL + _k0); \
    }                                                                          \
} while (0)

    float acc[4][8][4];
#pragma unroll
    for (int i = 0; i < 4; i++)
#pragma unroll
        for (int j = 0; j < 8; j++)
#pragma unroll
            for (int e = 0; e < 4; e++) acc[i][j][e] = 0.f;

    const int arow_l = ((lane >> 3) & 1) * 8 + (lane & 7);
    const int akoff  = (lane >> 4) * 8;
    // B x4 lane mapping: 16 n-rows per x4, two k-halves
    const int brow4  = (lane & 7) + ((lane >> 4) << 3);
    const int bko4   = ((lane >> 3) & 1) * 16;      // bytes

    PREFETCH(0, 0); CP_COMMIT();
    PREFETCH(1, 1); CP_COMMIT();
    PREFETCH(2, 2); CP_COMMIT();

    const int NCHUNK = DMODEL / BK;   // 32
    for (int c = 0; c < NCHUNK; c++) {
        if (c + 3 <= NCHUNK)      { CP_WAIT(2); }
        else if (c + 2 == NCHUNK) { CP_WAIT(1); }
        else                      { CP_WAIT(0); }
        __syncthreads();

        const uint32_t stb = sbase + (uint32_t)(c & 3) * STAGE_B2;
#pragma unroll
        for (int ks = 0; ks < 2; ks++) {
            uint32_t a[4][4], b4[4][4];
#pragma unroll
            for (int mt = 0; mt < 4; mt++) {
                uint32_t ad = stb + (uint32_t)(wm * 64 + mt * 16 + arow_l) * PITCHB
                                  + (uint32_t)(ks * 16 + akoff) * 2;
                ldsm_x4(a[mt], ad);
            }
#pragma unroll
            for (int np = 0; np < 4; np++) {
                uint32_t bd = stb + MAT_B
                                  + (uint32_t)(wn * 64 + np * 16 + brow4) * PITCHB
                                  + (uint32_t)(ks * 32 + bko4);
                ldsm_x4(b4[np], bd);
            }
#pragma unroll
            for (int mt = 0; mt < 4; mt++)
#pragma unroll
                for (int nt = 0; nt < 8; nt++) {
                    uint32_t bfr[2] = { b4[nt >> 1][(nt & 1) * 2 + 0],
                                        b4[nt >> 1][(nt & 1) * 2 + 1] };
                    mma_f16(acc[mt][nt], a[mt], bfr);
                }
        }

        if (c + 3 < NCHUNK) { PREFETCH((c + 3) & 3, c + 3); CP_COMMIT(); }
    }

    const int g     = lane >> 2;
    const int cpair = (lane & 3) * 2;
    if (mode == 0) {
        __half* C16 = (z == 0) ? g_q16 : (z == 1) ? g_k16 : g_v16;
#pragma unroll
        for (int mt = 0; mt < 4; mt++) {
            int row0 = m0 + wm * 64 + mt * 16 + g;
#pragma unroll
            for (int nt = 0; nt < 8; nt++) {
                int col = n0 + wn * 64 + nt * 8 + cpair;
                float bx = bias[col], by = bias[col + 1];
#pragma unroll
                for (int rr = 0; rr < 2; rr++) {
                    size_t off = (size_t)(row0 + rr * 8) * DMODEL + col;
                    *(__half2*)(C16 + off) =
                        __floats2half2_rn(acc[mt][nt][rr * 2 + 0] + bx,
                                          acc[mt][nt][rr * 2 + 1] + by);
                }
            }
        }
    } else {
        float* C = outp;
#pragma unroll
        for (int mt = 0; mt < 4; mt++) {
            int row0 = m0 + wm * 64 + mt * 16 + g;
#pragma unroll
            for (int nt = 0; nt < 8; nt++) {
                int col = n0 + wn * 64 + nt * 8 + cpair;
                float bx = bias[col], by = bias[col + 1];
                *(float2*)(C + (size_t)row0 * DMODEL + col) =
                    make_float2(acc[mt][nt][0] + bx, acc[mt][nt][1] + by);
                *(float2*)(C + (size_t)(row0 + 8) * DMODEL + col) =
                    make_float2(acc[mt][nt][2] + bx, acc[mt][nt][3] + by);
            }
        }
    }
#undef PREFETCH
}

// ============================================================
// Banded flash-attention, single fp16 Q/K/V, split-fp16 P.
// CTA = (128 queries, head, batch); 8 warps; warp = 16 query rows.
// smem: Q 128x72h, K 256x72h, V 256x72h = 92160 B -> 2 CTAs/SM.
// ============================================================
#define APITCHB  144
#define A_Q      0
#define A_K      18432              // 128*144
#define A_V      55296              // +256*144
#define ATTN_SMEM 92160

__global__ __launch_bounds__(256, 2) void attn_mma_kernel()
{
    extern __shared__ char sm[];
    const uint32_t sb = smem_u32(sm);

    const int tid  = threadIdx.x;
    const int lane = tid & 31;
    const int w    = tid >> 5;          // 0..7
    const int b    = blockIdx.z;
    const int h    = blockIdx.y;
    const int q0   = blockIdx.x * 128;
    const int kbase = q0 - WIN;
    const size_t tok0 = (size_t)b * SEQ;
    const int coff = h * HDIM;

    // ---- group 0: Q (128 rows) + K (256 rows); group 1: V (256 rows) ----
#pragma unroll
    for (int i = 0; i < 4; i++) {
        int task = tid + i * 256;          // 1024 tasks
        int row = task >> 3, seg = task & 7;
        uint32_t d = sb + A_Q + (uint32_t)row * APITCHB + (uint32_t)seg * 16;
        cp_async16(d, g_q16 + (tok0 + q0 + row) * DMODEL + coff + seg * 8);
    }
#pragma unroll
    for (int i = 0; i < 8; i++) {
        int task = tid + i * 256;          // 2048 tasks
        int row = task >> 3, seg = task & 7;
        int kg = kbase + row;
        int kgc = min(max(kg, 0), SEQ - 1);
        uint32_t sz = (kg >= 0 && kg < SEQ) ? 16u : 0u;
        uint32_t d = sb + A_K + (uint32_t)row * APITCHB + (uint32_t)seg * 16;
        cp_async16z(d, g_k16 + (tok0 + kgc) * DMODEL + coff + seg * 8, sz);
    }
    CP_COMMIT();
#pragma unroll
    for (int i = 0; i < 8; i++) {
        int task = tid + i * 256;
        int row = task >> 3, seg = task & 7;
        int kg = kbase + row;
        int kgc = min(max(kg, 0), SEQ - 1);
        uint32_t sz = (kg >= 0 && kg < SEQ) ? 16u : 0u;
        uint32_t d = sb + A_V + (uint32_t)row * APITCHB + (uint32_t)seg * 16;
        cp_async16z(d, g_v16 + (tok0 + kgc) * DMODEL + coff + seg * 8, sz);
    }
    CP_COMMIT();

    CP_WAIT(1);
    __syncthreads();

    // ---- Q fragments ----
    const int arow = w * 16 + ((lane >> 3) & 1) * 8 + (lane & 7);
    const int akoff = (lane >> 4) * 8;
    uint32_t qf[4][4];
#pragma unroll
    for (int kc = 0; kc < 4; kc++) {
        uint32_t ad = sb + A_Q + (uint32_t)arow * APITCHB + (uint32_t)(kc * 16 + akoff) * 2;
        ldsm_x4(qf[kc], ad);
    }

    // ---- QK: S[16][144], 18 n-tiles as 9 pairs via ldsm_x4, 1 pass ----
    float s[18][4];
#pragma unroll
    for (int t = 0; t < 18; t++)
#pragma unroll
        for (int e = 0; e < 4; e++) s[t][e] = 0.f;

    const int krow4 = (lane & 7) + ((lane >> 4) << 3);
    const int kko4  = ((lane >> 3) & 1) * 16;       // bytes
#pragma unroll
    for (int u = 0; u < 9; u++) {
        int ntb = 2 * w + 2 * u;
        uint32_t kb_addr = sb + A_K + (uint32_t)(ntb * 8 + krow4) * APITCHB + (uint32_t)kko4;
#pragma unroll
        for (int kc = 0; kc < 4; kc++) {
            uint32_t k4[4];
            ldsm_x4(k4, kb_addr + (uint32_t)kc * 32);
            uint32_t b0[2] = { k4[0], k4[1] }, b1[2] = { k4[2], k4[3] };
            mma_f16(s[2 * u],     qf[kc], b0);
            mma_f16(s[2 * u + 1], qf[kc], b1);
        }
    }

    // ---- mask + softmax ----
    const int g  = lane >> 2;
    const int c2 = (lane & 3) * 2;
    const int qg0 = q0 + w * 16 + g;
    const int qg1 = qg0 + 8;
    const float scale = 0.125f;

    float m0 = -1e30f, m1 = -1e30f;
#pragma unroll
    for (int t = 0; t < 18; t++) {
        int j0 = (2 * w + t) * 8 + c2;
        int kg0 = kbase + j0, kg1 = kg0 + 1;
        bool in0 = (kg0 >= 0) && (kg0 < SEQ);
        bool in1 = (kg1 >= 0) && (kg1 < SEQ);
        int d00 = kg0 - qg0, d10 = kg1 - qg0, d01 = kg0 - qg1, d11 = kg1 - qg1;
        s[t][0] = (in0 && d00 <= WIN && d00 >= -WIN) ? s[t][0] * scale : -1e30f;
        s[t][1] = (in1 && d10 <= WIN && d10 >= -WIN) ? s[t][1] * scale : -1e30f;
        s[t][2] = (in0 && d01 <= WIN && d01 >= -WIN) ? s[t][2] * scale : -1e30f;
        s[t][3] = (in1 && d11 <= WIN && d11 >= -WIN) ? s[t][3] * scale : -1e30f;
        m0 = fmaxf(m0, fmaxf(s[t][0], s[t][1]));
        m1 = fmaxf(m1, fmaxf(s[t][2], s[t][3]));
    }
    m0 = fmaxf(m0, __shfl_xor_sync(0xffffffffu, m0, 1));
    m0 = fmaxf(m0, __shfl_xor_sync(0xffffffffu, m0, 2));
    m1 = fmaxf(m1, __shfl_xor_sync(0xffffffffu, m1, 1));
    m1 = fmaxf(m1, __shfl_xor_sync(0xffffffffu, m1, 2));

    float r0 = 0.f, r1 = 0.f;
#pragma unroll
    for (int t = 0; t < 18; t++) {
        s[t][0] = __expf(s[t][0] - m0);
        s[t][1] = __expf(s[t][1] - m0);
        s[t][2] = __expf(s[t][2] - m1);
        s[t][3] = __expf(s[t][3] - m1);
        r0 += s[t][0] + s[t][1];
        r1 += s[t][2] + s[t][3];
    }
    r0 += __shfl_xor_sync(0xffffffffu, r0, 1);
    r0 += __shfl_xor_sync(0xffffffffu, r0, 2);
    r1 += __shfl_xor_sync(0xffffffffu, r1, 1);
    r1 += __shfl_xor_sync(0xffffffffu, r1, 2);
    float inv0 = 1.f / r0, inv1 = 1.f / r1;

    // ---- pack P into split-fp16 A-fragments (P = ph + pl, near-exact) ----
    uint32_t ph01[18], ph23[18], pl01[18], pl23[18];
#pragma unroll
    for (int t = 0; t < 18; t++) {
        float p0 = s[t][0] * inv0, p1 = s[t][1] * inv0;
        float p2 = s[t][2] * inv1, p3 = s[t][3] * inv1;
        __half2 h2 = __floats2half2_rn(p0, p1);
        ph01[t] = *(uint32_t*)&h2;
        pl01[t] = pack_hf2(p0 - __half2float(h2.x), p1 - __half2float(h2.y));
        h2 = __floats2half2_rn(p2, p3);
        ph23[t] = *(uint32_t*)&h2;
        pl23[t] = pack_hf2(p2 - __half2float(h2.x), p3 - __half2float(h2.y));
    }

    CP_WAIT(0);
    __syncthreads();

    // ---- PV: out[16][64], 2-pass (P hi + P lo), V single fp16 ----
    float o[8][4];
#pragma unroll
    for (int nt = 0; nt < 8; nt++)
#pragma unroll
        for (int e = 0; e < 4; e++) o[nt][e] = 0.f;

    const int vrow_l = ((lane >> 3) & 1) * 8 + (lane & 7);
#pragma unroll
    for (int jl = 0; jl < 9; jl++) {
        uint32_t ah[4] = { ph01[2 * jl], ph23[2 * jl], ph01[2 * jl + 1], ph23[2 * jl + 1] };
        uint32_t al[4] = { pl01[2 * jl], pl23[2 * jl], pl01[2 * jl + 1], pl23[2 * jl + 1] };
        int keyb = (w + jl) * 16;
        uint32_t va_base = sb + A_V + (uint32_t)(keyb + vrow_l) * APITCHB;
#pragma unroll
        for (int nt = 0; nt < 8; nt++) {
            uint32_t vf[2];
            ldsm_x2t(vf, va_base + (uint32_t)nt * 16);
            mma_f16(o[nt], ah, vf);
            mma_f16(o[nt], al, vf);
        }
    }

    size_t row0 = tok0 + qg0;
    size_t row1 = tok0 + qg1;
#pragma unroll
    for (int nt = 0; nt < 8; nt++) {
        int col = coff + nt * 8 + c2;
        *(__half2*)(g_a16 + row0 * DMODEL + col) = __floats2half2_rn(o[nt][0], o[nt][1]);
        *(__half2*)(g_a16 + row1 * DMODEL + col) = __floats2half2_rn(o[nt][2], o[nt][3]);
    }
}

// ============================================================
extern "C" void kernel_launch(void* const* d_in, const int* in_sizes, int n_in,
                              void* d_out, int out_size)
{
    const float* x  = (const float*)d_in[0];
    const float* Wq = (const float*)d_in[1];
    const float* bq = (const float*)d_in[2];
    const float* Wk = (const float*)d_in[3];
    const float* bk = (const float*)d_in[4];
    const float* Wv = (const float*)d_in[5];
    const float* bv = (const float*)d_in[6];
    const float* Wo = (const float*)d_in[7];
    const float* bo = (const float*)d_in[8];
    float* out = (float*)d_out;

    cudaFuncSetAttribute(hmma_gemm_kernel, cudaFuncAttributeMaxDynamicSharedMemorySize, GEMM_SMEM);
    cudaFuncSetAttribute(attn_mma_kernel, cudaFuncAttributeMaxDynamicSharedMemorySize, ATTN_SMEM);

    prep_kernel<<<MTOT + 4096, 256>>>(x, Wq, Wk, Wv, Wo);

    dim3 gq(DMODEL / 128, MTOT / 128, 3);
    hmma_gemm_kernel<<<gq, 128, GEMM_SMEM>>>(0, bq, bk, bv, nullptr);

    dim3 ga(SEQ / 128, NHEADS, BATCH);
    attn_mma_kernel<<<ga, 256, ATTN_SMEM>>>();

    dim3 go(DMODEL / 128, MTOT / 128, 1);
    hmma_gemm_kernel<<<go, 128, GEMM_SMEM>>>(1, bo, nullptr, nullptr, out);
}

// round 14
// speedup vs baseline: 1.0824x; 1.0824x over previous
#include <cuda_runtime.h>
#include <cuda_bf16.h>
#include <cuda_fp16.h>
#include <math.h>
#include <stdint.h>

#define BATCH   2
#define SEQ     2048
#define DMODEL  1024
#define NHEADS  16
#define HDIM    64
#define WIN     64
#define MTOT    (BATCH*SEQ)   // 4096
#define WSZ     (DMODEL*DMODEL)

// ---------------- scratch (static device globals) ----------------
__device__ __half g_x16[MTOT*DMODEL];          // x rounded to fp16
__device__ __half g_w16[4*WSZ];                // transposed [n][k], fp16
__device__ __half g_q16[MTOT*DMODEL];
__device__ __half g_k16[MTOT*DMODEL];
__device__ __half g_v16[MTOT*DMODEL];
__device__ __half g_a16[MTOT*DMODEL];          // attention out, fp16

// ---------------- PTX helpers (non-'a' features only) ----------------
__device__ __forceinline__ uint32_t smem_u32(const void* p) {
    uint32_t a;
    asm("{ .reg .u64 t; cvta.to.shared.u64 t, %1; cvt.u32.u64 %0, t; }" : "=r"(a) : "l"(p));
    return a;
}
__device__ __forceinline__ void cp_async16(uint32_t s, const void* g) {
    asm volatile("cp.async.cg.shared.global [%0], [%1], 16;" :: "r"(s), "l"(g));
}
__device__ __forceinline__ void cp_async16z(uint32_t s, const void* g, uint32_t srcsz) {
    asm volatile("cp.async.cg.shared.global [%0], [%1], 16, %2;" :: "r"(s), "l"(g), "r"(srcsz));
}
#define CP_COMMIT() asm volatile("cp.async.commit_group;" ::: "memory")
#define CP_WAIT(n)  asm volatile("cp.async.wait_group %0;" :: "n"(n) : "memory")

__device__ __forceinline__ void ldsm_x4(uint32_t* r, uint32_t a) {
    asm volatile("ldmatrix.sync.aligned.m8n8.x4.shared.b16 {%0,%1,%2,%3}, [%4];"
        : "=r"(r[0]), "=r"(r[1]), "=r"(r[2]), "=r"(r[3]) : "r"(a));
}
__device__ __forceinline__ void ldsm_x2t(uint32_t* r, uint32_t a) {
    asm volatile("ldmatrix.sync.aligned.m8n8.x2.trans.shared.b16 {%0,%1}, [%2];"
        : "=r"(r[0]), "=r"(r[1]) : "r"(a));
}
__device__ __forceinline__ void mma_f16(float* d, const uint32_t* a, const uint32_t* b) {
    asm volatile(
        "mma.sync.aligned.m16n8k16.row.col.f32.f16.f16.f32 "
        "{%0,%1,%2,%3}, {%4,%5,%6,%7}, {%8,%9}, {%0,%1,%2,%3};"
        : "+f"(d[0]), "+f"(d[1]), "+f"(d[2]), "+f"(d[3])
        : "r"(a[0]), "r"(a[1]), "r"(a[2]), "r"(a[3]), "r"(b[0]), "r"(b[1]));
}

__device__ __forceinline__ uint32_t pack_hf2(float x, float y) {
    __half2 h = __floats2half2_rn(x, y);
    return *(uint32_t*)&h;
}

// ============================================================
// Fused prep: blocks [0,4096) convert x -> fp16;
//             blocks [4096,8192) transpose W[k][n] -> Wt[n][k] fp16.
// ============================================================
__global__ __launch_bounds__(256) void prep_kernel(
    const float* __restrict__ x,
    const float* __restrict__ Wq, const float* __restrict__ Wk,
    const float* __restrict__ Wv, const float* __restrict__ Wo)
{
    __shared__ float tile[32][33];
    int bid = blockIdx.x;
    if (bid < MTOT) {
        size_t off = (size_t)bid * DMODEL + threadIdx.x * 4;
        float4 v = *(const float4*)(x + off);
        *(__half2*)(g_x16 + off)     = __floats2half2_rn(v.x, v.y);
        *(__half2*)(g_x16 + off + 2) = __floats2half2_rn(v.z, v.w);
    } else {
        int t = bid - MTOT;                 // 0..4095
        int z = t >> 10;                    // 0..3
        int tt = t & 1023;                  // 0..1023
        const float* W = (z == 0) ? Wq : (z == 1) ? Wk : (z == 2) ? Wv : Wo;
        __half* T = g_w16 + (size_t)z * WSZ;
        int kb = (tt >> 5) * 32, nb = (tt & 31) * 32;
        int tx = threadIdx.x & 31, ty = threadIdx.x >> 5;   // ty 0..7
#pragma unroll
        for (int i = 0; i < 4; i++)
            tile[ty + 8 * i][tx] = W[(size_t)(kb + ty + 8 * i) * DMODEL + nb + tx];
        __syncthreads();
#pragma unroll
        for (int i = 0; i < 4; i++) {
            T[(size_t)(nb + ty + 8 * i) * DMODEL + kb + tx] =
                __float2half_rn(tile[tx][ty + 8 * i]);
        }
    }
}

// ============================================================
// Single-pass fp16 HMMA GEMM (exact R12 config): C = A16 @ W16^T + bias
// CTA tile 128x128, BK=32, 8 warps (2x4), warp tile 64x32.
// 4-stage cp.async, single __syncthreads per chunk; 80 KB -> 2 CTAs/SM.
// ============================================================
#define BK       32
#define PITCHB   80                    // bytes per SMEM row (40 fp16)
#define MAT_B    (128*PITCHB)          // 10240 B per matrix tile
#define STAGE_B2 (2*MAT_B)             // 20480 B per stage
#define NSTAGE   4
#define GEMM_SMEM (NSTAGE*STAGE_B2)    // 81920 B
#define ROW64B   (64*PITCHB)

__global__ __launch_bounds__(256) void hmma_gemm_kernel(
    int mode, const float* __restrict__ b0, const float* __restrict__ b1,
    const float* __restrict__ b2, float* __restrict__ outp)
{
    extern __shared__ char sm[];
    const uint32_t sbase = smem_u32(sm);

    const int tid  = threadIdx.x;
    const int lane = tid & 31;
    const int wid  = tid >> 5;
    const int wm   = wid >> 2;
    const int wn   = wid & 3;
    const int m0   = blockIdx.y * 128;
    const int n0   = blockIdx.x * 128;
    const int z    = blockIdx.z;

    const __half *A, *B;
    const float* bias;
    if (mode == 0) {
        A = g_x16;
        B = g_w16 + (size_t)z * WSZ;
        bias = (z == 0) ? b0 : (z == 1) ? b1 : b2;
    } else {
        A = g_a16;
        B = g_w16 + 3ull * WSZ;
        bias = b0;
    }

    const int rowA = tid >> 2;
    const int seg  = tid & 3;
    const uint32_t s0 = (uint32_t)rowA * PITCHB + (uint32_t)seg * 16;
    const __half* pA = A + (size_t)(m0 + rowA) * DMODEL + seg * 8;
    const __half* pB = B + (size_t)(n0 + rowA) * DMODEL + seg * 8;

#define PREFETCH(stage, cc) do {                                             \
    const int _k0 = (cc) * BK;                                               \
    const uint32_t _sb = sbase + (uint32_t)(stage) * STAGE_B2 + s0;          \
    cp_async16(_sb,                  pA + _k0);                              \
    cp_async16(_sb + ROW64B,         pA + 64 * DMODEL + _k0);                \
    cp_async16(_sb + MAT_B,          pB + _k0);                              \
    cp_async16(_sb + MAT_B + ROW64B, pB + 64 * DMODEL + _k0);                \
} while (0)

    float acc[4][4][4];
#pragma unroll
    for (int i = 0; i < 4; i++)
#pragma unroll
        for (int j = 0; j < 4; j++)
#pragma unroll
            for (int e = 0; e < 4; e++) acc[i][j][e] = 0.f;

    const int arow_l = ((lane >> 3) & 1) * 8 + (lane & 7);
    const int akoff  = (lane >> 4) * 8;
    const int brow4  = (lane & 7) + ((lane >> 4) << 3);
    const int bko4   = ((lane >> 3) & 1) * 16;      // bytes

    PREFETCH(0, 0); CP_COMMIT();
    PREFETCH(1, 1); CP_COMMIT();
    PREFETCH(2, 2); CP_COMMIT();

    const int NCHUNK = DMODEL / BK;   // 32
    for (int c = 0; c < NCHUNK; c++) {
        if (c + 3 <= NCHUNK)      { CP_WAIT(2); }
        else if (c + 2 == NCHUNK) { CP_WAIT(1); }
        else                      { CP_WAIT(0); }
        __syncthreads();

        const uint32_t stb = sbase + (uint32_t)(c & 3) * STAGE_B2;
#pragma unroll
        for (int ks = 0; ks < 2; ks++) {
            uint32_t a[4][4], b4[2][4];
#pragma unroll
            for (int mt = 0; mt < 4; mt++) {
                uint32_t ad = stb + (uint32_t)(wm * 64 + mt * 16 + arow_l) * PITCHB
                                  + (uint32_t)(ks * 16 + akoff) * 2;
                ldsm_x4(a[mt], ad);
            }
#pragma unroll
            for (int np = 0; np < 2; np++) {
                uint32_t bd = stb + MAT_B
                                  + (uint32_t)(wn * 32 + np * 16 + brow4) * PITCHB
                                  + (uint32_t)(ks * 32 + bko4);
                ldsm_x4(b4[np], bd);
            }
#pragma unroll
            for (int mt = 0; mt < 4; mt++)
#pragma unroll
                for (int nt = 0; nt < 4; nt++) {
                    uint32_t bfr[2] = { b4[nt >> 1][(nt & 1) * 2 + 0],
                                        b4[nt >> 1][(nt & 1) * 2 + 1] };
                    mma_f16(acc[mt][nt], a[mt], bfr);
                }
        }

        if (c + 3 < NCHUNK) { PREFETCH((c + 3) & 3, c + 3); CP_COMMIT(); }
    }

    const int g     = lane >> 2;
    const int cpair = (lane & 3) * 2;
    if (mode == 0) {
        __half* C16 = (z == 0) ? g_q16 : (z == 1) ? g_k16 : g_v16;
#pragma unroll
        for (int mt = 0; mt < 4; mt++) {
            int row0 = m0 + wm * 64 + mt * 16 + g;
#pragma unroll
            for (int nt = 0; nt < 4; nt++) {
                int col = n0 + wn * 32 + nt * 8 + cpair;
                float bx = bias[col], by = bias[col + 1];
#pragma unroll
                for (int rr = 0; rr < 2; rr++) {
                    size_t off = (size_t)(row0 + rr * 8) * DMODEL + col;
                    *(__half2*)(C16 + off) =
                        __floats2half2_rn(acc[mt][nt][rr * 2 + 0] + bx,
                                          acc[mt][nt][rr * 2 + 1] + by);
                }
            }
        }
    } else {
        float* C = outp;
#pragma unroll
        for (int mt = 0; mt < 4; mt++) {
            int row0 = m0 + wm * 64 + mt * 16 + g;
#pragma unroll
            for (int nt = 0; nt < 4; nt++) {
                int col = n0 + wn * 32 + nt * 8 + cpair;
                float bx = bias[col], by = bias[col + 1];
                *(float2*)(C + (size_t)row0 * DMODEL + col) =
                    make_float2(acc[mt][nt][0] + bx, acc[mt][nt][1] + by);
                *(float2*)(C + (size_t)(row0 + 8) * DMODEL + col) =
                    make_float2(acc[mt][nt][2] + bx, acc[mt][nt][3] + by);
            }
        }
    }
#undef PREFETCH
}

// ============================================================
// Banded flash-attention, single fp16 Q/K/V and single fp16 P.
// CTA = (128 queries, head, batch); 8 warps; warp = 16 query rows.
// smem: Q 128x72h, K 256x72h, V 256x72h = 92160 B -> 2 CTAs/SM.
// ============================================================
#define APITCHB  144
#define A_Q      0
#define A_K      18432              // 128*144
#define A_V      55296              // +256*144
#define ATTN_SMEM 92160

__global__ __launch_bounds__(256, 2) void attn_mma_kernel()
{
    extern __shared__ char sm[];
    const uint32_t sb = smem_u32(sm);

    const int tid  = threadIdx.x;
    const int lane = tid & 31;
    const int w    = tid >> 5;          // 0..7
    const int b    = blockIdx.z;
    const int h    = blockIdx.y;
    const int q0   = blockIdx.x * 128;
    const int kbase = q0 - WIN;
    const size_t tok0 = (size_t)b * SEQ;
    const int coff = h * HDIM;

    // ---- group 0: Q (128 rows) + K (256 rows); group 1: V (256 rows) ----
#pragma unroll
    for (int i = 0; i < 4; i++) {
        int task = tid + i * 256;          // 1024 tasks
        int row = task >> 3, seg = task & 7;
        uint32_t d = sb + A_Q + (uint32_t)row * APITCHB + (uint32_t)seg * 16;
        cp_async16(d, g_q16 + (tok0 + q0 + row) * DMODEL + coff + seg * 8);
    }
#pragma unroll
    for (int i = 0; i < 8; i++) {
        int task = tid + i * 256;          // 2048 tasks
        int row = task >> 3, seg = task & 7;
        int kg = kbase + row;
        int kgc = min(max(kg, 0), SEQ - 1);
        uint32_t sz = (kg >= 0 && kg < SEQ) ? 16u : 0u;
        uint32_t d = sb + A_K + (uint32_t)row * APITCHB + (uint32_t)seg * 16;
        cp_async16z(d, g_k16 + (tok0 + kgc) * DMODEL + coff + seg * 8, sz);
    }
    CP_COMMIT();
#pragma unroll
    for (int i = 0; i < 8; i++) {
        int task = tid + i * 256;
        int row = task >> 3, seg = task & 7;
        int kg = kbase + row;
        int kgc = min(max(kg, 0), SEQ - 1);
        uint32_t sz = (kg >= 0 && kg < SEQ) ? 16u : 0u;
        uint32_t d = sb + A_V + (uint32_t)row * APITCHB + (uint32_t)seg * 16;
        cp_async16z(d, g_v16 + (tok0 + kgc) * DMODEL + coff + seg * 8, sz);
    }
    CP_COMMIT();

    CP_WAIT(1);
    __syncthreads();

    // ---- Q fragments ----
    const int arow = w * 16 + ((lane >> 3) & 1) * 8 + (lane & 7);
    const int akoff = (lane >> 4) * 8;
    uint32_t qf[4][4];
#pragma unroll
    for (int kc = 0; kc < 4; kc++) {
        uint32_t ad = sb + A_Q + (uint32_t)arow * APITCHB + (uint32_t)(kc * 16 + akoff) * 2;
        ldsm_x4(qf[kc], ad);
    }

    // ---- QK: S[16][144], 18 n-tiles as 9 pairs via ldsm_x4, 1 pass ----
    float s[18][4];
#pragma unroll
    for (int t = 0; t < 18; t++)
#pragma unroll
        for (int e = 0; e < 4; e++) s[t][e] = 0.f;

    const int krow4 = (lane & 7) + ((lane >> 4) << 3);
    const int kko4  = ((lane >> 3) & 1) * 16;       // bytes
#pragma unroll
    for (int u = 0; u < 9; u++) {
        int ntb = 2 * w + 2 * u;
        uint32_t kb_addr = sb + A_K + (uint32_t)(ntb * 8 + krow4) * APITCHB + (uint32_t)kko4;
#pragma unroll
        for (int kc = 0; kc < 4; kc++) {
            uint32_t k4[4];
            ldsm_x4(k4, kb_addr + (uint32_t)kc * 32);
            uint32_t b0[2] = { k4[0], k4[1] }, b1[2] = { k4[2], k4[3] };
            mma_f16(s[2 * u],     qf[kc], b0);
            mma_f16(s[2 * u + 1], qf[kc], b1);
        }
    }

    // ---- mask + softmax ----
    const int g  = lane >> 2;
    const int c2 = (lane & 3) * 2;
    const int qg0 = q0 + w * 16 + g;
    const int qg1 = qg0 + 8;
    const float scale = 0.125f;

    float m0 = -1e30f, m1 = -1e30f;
#pragma unroll
    for (int t = 0; t < 18; t++) {
        int j0 = (2 * w + t) * 8 + c2;
        int kg0 = kbase + j0, kg1 = kg0 + 1;
        bool in0 = (kg0 >= 0) && (kg0 < SEQ);
        bool in1 = (kg1 >= 0) && (kg1 < SEQ);
        int d00 = kg0 - qg0, d10 = kg1 - qg0, d01 = kg0 - qg1, d11 = kg1 - qg1;
        s[t][0] = (in0 && d00 <= WIN && d00 >= -WIN) ? s[t][0] * scale : -1e30f;
        s[t][1] = (in1 && d10 <= WIN && d10 >= -WIN) ? s[t][1] * scale : -1e30f;
        s[t][2] = (in0 && d01 <= WIN && d01 >= -WIN) ? s[t][2] * scale : -1e30f;
        s[t][3] = (in1 && d11 <= WIN && d11 >= -WIN) ? s[t][3] * scale : -1e30f;
        m0 = fmaxf(m0, fmaxf(s[t][0], s[t][1]));
        m1 = fmaxf(m1, fmaxf(s[t][2], s[t][3]));
    }
    m0 = fmaxf(m0, __shfl_xor_sync(0xffffffffu, m0, 1));
    m0 = fmaxf(m0, __shfl_xor_sync(0xffffffffu, m0, 2));
    m1 = fmaxf(m1, __shfl_xor_sync(0xffffffffu, m1, 1));
    m1 = fmaxf(m1, __shfl_xor_sync(0xffffffffu, m1, 2));

    float r0 = 0.f, r1 = 0.f;
#pragma unroll
    for (int t = 0; t < 18; t++) {
        s[t][0] = __expf(s[t][0] - m0);
        s[t][1] = __expf(s[t][1] - m0);
        s[t][2] = __expf(s[t][2] - m1);
        s[t][3] = __expf(s[t][3] - m1);
        r0 += s[t][0] + s[t][1];
        r1 += s[t][2] + s[t][3];
    }
    r0 += __shfl_xor_sync(0xffffffffu, r0, 1);
    r0 += __shfl_xor_sync(0xffffffffu, r0, 2);
    r1 += __shfl_xor_sync(0xffffffffu, r1, 1);
    r1 += __shfl_xor_sync(0xffffffffu, r1, 2);
    float inv0 = 1.f / r0, inv1 = 1.f / r1;

    // ---- pack P into single-fp16 A-fragments ----
    uint32_t ph01[18], ph23[18];
#pragma unroll
    for (int t = 0; t < 18; t++) {
        ph01[t] = pack_hf2(s[t][0] * inv0, s[t][1] * inv0);
        ph23[t] = pack_hf2(s[t][2] * inv1, s[t][3] * inv1);
    }

    CP_WAIT(0);
    __syncthreads();

    // ---- PV: out[16][64], single pass, V single fp16 ----
    float o[8][4];
#pragma unroll
    for (int nt = 0; nt < 8; nt++)
#pragma unroll
        for (int e = 0; e < 4; e++) o[nt][e] = 0.f;

    const int vrow_l = ((lane >> 3) & 1) * 8 + (lane & 7);
#pragma unroll
    for (int jl = 0; jl < 9; jl++) {
        uint32_t ah[4] = { ph01[2 * jl], ph23[2 * jl], ph01[2 * jl + 1], ph23[2 * jl + 1] };
        int keyb = (w + jl) * 16;
        uint32_t va_base = sb + A_V + (uint32_t)(keyb + vrow_l) * APITCHB;
#pragma unroll
        for (int nt = 0; nt < 8; nt++) {
            uint32_t vf[2];
            ldsm_x2t(vf, va_base + (uint32_t)nt * 16);
            mma_f16(o[nt], ah, vf);
        }
    }

    size_t row0 = tok0 + qg0;
    size_t row1 = tok0 + qg1;
#pragma unroll
    for (int nt = 0; nt < 8; nt++) {
        int col = coff + nt * 8 + c2;
        *(__half2*)(g_a16 + row0 * DMODEL + col) = __floats2half2_rn(o[nt][0], o[nt][1]);
        *(__half2*)(g_a16 + row1 * DMODEL + col) = __floats2half2_rn(o[nt][2], o[nt][3]);
    }
}

// ============================================================
extern "C" void kernel_launch(void* const* d_in, const int* in_sizes, int n_in,
                              void* d_out, int out_size)
{
    const float* x  = (const float*)d_in[0];
    const float* Wq = (const float*)d_in[1];
    const float* bq = (const float*)d_in[2];
    const float* Wk = (const float*)d_in[3];
    const float* bk = (const float*)d_in[4];
    const float* Wv = (const float*)d_in[5];
    const float* bv = (const float*)d_in[6];
    const float* Wo = (const float*)d_in[7];
    const float* bo = (const float*)d_in[8];
    float* out = (float*)d_out;

    cudaFuncSetAttribute(hmma_gemm_kernel, cudaFuncAttributeMaxDynamicSharedMemorySize, GEMM_SMEM);
    cudaFuncSetAttribute(attn_mma_kernel, cudaFuncAttributeMaxDynamicSharedMemorySize, ATTN_SMEM);

    prep_kernel<<<MTOT + 4096, 256>>>(x, Wq, Wk, Wv, Wo);

    dim3 gq(DMODEL / 128, MTOT / 128, 3);
    hmma_gemm_kernel<<<gq, 256, GEMM_SMEM>>>(0, bq, bk, bv, nullptr);

    dim3 ga(SEQ / 128, NHEADS, BATCH);
    attn_mma_kernel<<<ga, 256, ATTN_SMEM>>>();

    dim3 go(DMODEL / 128, MTOT / 128, 1);
    hmma_gemm_kernel<<<go, 256, GEMM_SMEM>>>(1, bo, nullptr, nullptr, out);
}

// round 15
// speedup vs baseline: 1.1394x; 1.0527x over previous
#include <cuda_runtime.h>
#include <cuda_bf16.h>
#include <cuda_fp16.h>
#include <math.h>
#include <stdint.h>

#define BATCH   2
#define SEQ     2048
#define DMODEL  1024
#define NHEADS  16
#define HDIM    64
#define WIN     64
#define MTOT    (BATCH*SEQ)   // 4096
#define WSZ     (DMODEL*DMODEL)

// ---------------- scratch (static device globals) ----------------
__device__ __half g_x16[MTOT*DMODEL];          // x rounded to fp16
__device__ __half g_w16[4*WSZ];                // ORIGINAL [k][n] layout, fp16
__device__ __half g_q16[MTOT*DMODEL];
__device__ __half g_k16[MTOT*DMODEL];
__device__ __half g_v16[MTOT*DMODEL];
__device__ __half g_a16[MTOT*DMODEL];          // attention out, fp16

// ---------------- PTX helpers (non-'a' features only) ----------------
__device__ __forceinline__ uint32_t smem_u32(const void* p) {
    uint32_t a;
    asm("{ .reg .u64 t; cvta.to.shared.u64 t, %1; cvt.u32.u64 %0, t; }" : "=r"(a) : "l"(p));
    return a;
}
__device__ __forceinline__ void cp_async16(uint32_t s, const void* g) {
    asm volatile("cp.async.cg.shared.global [%0], [%1], 16;" :: "r"(s), "l"(g));
}
__device__ __forceinline__ void cp_async16z(uint32_t s, const void* g, uint32_t srcsz) {
    asm volatile("cp.async.cg.shared.global [%0], [%1], 16, %2;" :: "r"(s), "l"(g), "r"(srcsz));
}
#define CP_COMMIT() asm volatile("cp.async.commit_group;" ::: "memory")
#define CP_WAIT(n)  asm volatile("cp.async.wait_group %0;" :: "n"(n) : "memory")

__device__ __forceinline__ void ldsm_x4(uint32_t* r, uint32_t a) {
    asm volatile("ldmatrix.sync.aligned.m8n8.x4.shared.b16 {%0,%1,%2,%3}, [%4];"
        : "=r"(r[0]), "=r"(r[1]), "=r"(r[2]), "=r"(r[3]) : "r"(a));
}
__device__ __forceinline__ void ldsm_x2t(uint32_t* r, uint32_t a) {
    asm volatile("ldmatrix.sync.aligned.m8n8.x2.trans.shared.b16 {%0,%1}, [%2];"
        : "=r"(r[0]), "=r"(r[1]) : "r"(a));
}
__device__ __forceinline__ void mma_f16(float* d, const uint32_t* a, const uint32_t* b) {
    asm volatile(
        "mma.sync.aligned.m16n8k16.row.col.f32.f16.f16.f32 "
        "{%0,%1,%2,%3}, {%4,%5,%6,%7}, {%8,%9}, {%0,%1,%2,%3};"
        : "+f"(d[0]), "+f"(d[1]), "+f"(d[2]), "+f"(d[3])
        : "r"(a[0]), "r"(a[1]), "r"(a[2]), "r"(a[3]), "r"(b[0]), "r"(b[1]));
}

__device__ __forceinline__ uint32_t pack_hf2(float x, float y) {
    __half2 h = __floats2half2_rn(x, y);
    return *(uint32_t*)&h;
}

// ============================================================
// Fused prep (all streaming, no transpose):
//   blocks [0,4096):      convert x -> fp16
//   blocks [4096,8192):   convert W (original [k][n] layout) -> fp16
// ============================================================
__global__ __launch_bounds__(256) void prep_kernel(
    const float* __restrict__ x,
    const float* __restrict__ Wq, const float* __restrict__ Wk,
    const float* __restrict__ Wv, const float* __restrict__ Wo)
{
    int bid = blockIdx.x;
    if (bid < MTOT) {
        size_t off = (size_t)bid * DMODEL + threadIdx.x * 4;
        float4 v = *(const float4*)(x + off);
        *(__half2*)(g_x16 + off)     = __floats2half2_rn(v.x, v.y);
        *(__half2*)(g_x16 + off + 2) = __floats2half2_rn(v.z, v.w);
    } else {
        int t = bid - MTOT;                 // 0..4095
        int z = t >> 10;
        int row = t & 1023;
        const float* W = (z == 0) ? Wq : (z == 1) ? Wk : (z == 2) ? Wv : Wo;
        size_t off = (size_t)row * DMODEL + threadIdx.x * 4;
        float4 v = *(const float4*)(W + off);
        size_t o = (size_t)z * WSZ + off;
        *(__half2*)(g_w16 + o)     = __floats2half2_rn(v.x, v.y);
        *(__half2*)(g_w16 + o + 2) = __floats2half2_rn(v.z, v.w);
    }
}

// ============================================================
// Single-pass fp16 HMMA GEMM: C = A16 @ W16 + bias, W in [k][n].
// CTA tile 128x128, BK=32, 8 warps (2x4), warp tile 64x32.
// A smem [128 m][32 k] pitch 80B; B smem [32 k][128 n] pitch 272B.
// B fragments via ldmatrix.trans (pattern validated in R5 GEMM + attn PV).
// 4-stage cp.async, single barrier per chunk; 75.8 KB -> 2 CTAs/SM.
// ============================================================
#define BK       32
#define PITCHB   80                    // A: bytes per SMEM row (40 fp16)
#define MAT_A    (128*PITCHB)          // 10240 B
#define BPITCH   272                   // B: bytes per SMEM row (128 fp16 + pad)
#define MAT_BB   (32*BPITCH)           // 8704 B
#define STAGE_SZ (MAT_A + MAT_BB)      // 18944 B
#define NSTAGE   4
#define GEMM_SMEM (NSTAGE*STAGE_SZ)    // 75776 B
#define ROW64B   (64*PITCHB)

__global__ __launch_bounds__(256) void hmma_gemm_kernel(
    int mode, const float* __restrict__ b0, const float* __restrict__ b1,
    const float* __restrict__ b2, float* __restrict__ outp)
{
    extern __shared__ char sm[];
    const uint32_t sbase = smem_u32(sm);

    const int tid  = threadIdx.x;
    const int lane = tid & 31;
    const int wid  = tid >> 5;
    const int wm   = wid >> 2;
    const int wn   = wid & 3;
    const int m0   = blockIdx.y * 128;
    const int n0   = blockIdx.x * 128;
    const int z    = blockIdx.z;

    const __half *A, *B;
    const float* bias;
    if (mode == 0) {
        A = g_x16;
        B = g_w16 + (size_t)z * WSZ;
        bias = (z == 0) ? b0 : (z == 1) ? b1 : b2;
    } else {
        A = g_a16;
        B = g_w16 + 3ull * WSZ;
        bias = b0;
    }

    // A loads: 128 rows x 4 segs (16B). B loads: 32 rows x 8 segs x 2 halves.
    const int rowA = tid >> 2;
    const int segA = tid & 3;
    const uint32_t sA0 = (uint32_t)rowA * PITCHB + (uint32_t)segA * 16;
    const __half* pA = A + (size_t)(m0 + rowA) * DMODEL + segA * 8;

    const int rowB = tid >> 3;          // 0..31 (k)
    const int segB = tid & 7;           // 16B segment within 64 n
    const uint32_t sB0 = MAT_A + (uint32_t)rowB * BPITCH + (uint32_t)segB * 16;
    const __half* pB = B + (size_t)rowB * DMODEL + n0 + segB * 8;

#define PREFETCH(stage, cc) do {                                              \
    const int _k0 = (cc) * BK;                                                \
    const uint32_t _sb = sbase + (uint32_t)(stage) * STAGE_SZ;                \
    cp_async16(_sb + sA0,          pA + _k0);                                 \
    cp_async16(_sb + sA0 + ROW64B, pA + 64 * DMODEL + _k0);                   \
    cp_async16(_sb + sB0,          pB + (size_t)_k0 * DMODEL);                \
    cp_async16(_sb + sB0 + 128,    pB + (size_t)_k0 * DMODEL + 64);           \
} while (0)

    float acc[4][4][4];
#pragma unroll
    for (int i = 0; i < 4; i++)
#pragma unroll
        for (int j = 0; j < 4; j++)
#pragma unroll
            for (int e = 0; e < 4; e++) acc[i][j][e] = 0.f;

    const int arow_l = ((lane >> 3) & 1) * 8 + (lane & 7);
    const int akoff  = (lane >> 4) * 8;
    const int btrow  = ((lane >> 3) & 1) * 8 + (lane & 7);   // trans-B k-row within k16

    PREFETCH(0, 0); CP_COMMIT();
    PREFETCH(1, 1); CP_COMMIT();
    PREFETCH(2, 2); CP_COMMIT();

    const int NCHUNK = DMODEL / BK;   // 32
    for (int c = 0; c < NCHUNK; c++) {
        if (c + 3 <= NCHUNK)      { CP_WAIT(2); }
        else if (c + 2 == NCHUNK) { CP_WAIT(1); }
        else                      { CP_WAIT(0); }
        __syncthreads();

        const uint32_t stb = sbase + (uint32_t)(c & 3) * STAGE_SZ;
#pragma unroll
        for (int ks = 0; ks < 2; ks++) {
            uint32_t a[4][4], bfr[4][2];
#pragma unroll
            for (int mt = 0; mt < 4; mt++) {
                uint32_t ad = stb + (uint32_t)(wm * 64 + mt * 16 + arow_l) * PITCHB
                                  + (uint32_t)(ks * 16 + akoff) * 2;
                ldsm_x4(a[mt], ad);
            }
#pragma unroll
            for (int nt = 0; nt < 4; nt++) {
                uint32_t bd = stb + MAT_A
                                  + (uint32_t)(ks * 16 + btrow) * BPITCH
                                  + (uint32_t)(wn * 32 + nt * 8) * 2;
                ldsm_x2t(bfr[nt], bd);
            }
#pragma unroll
            for (int mt = 0; mt < 4; mt++)
#pragma unroll
                for (int nt = 0; nt < 4; nt++)
                    mma_f16(acc[mt][nt], a[mt], bfr[nt]);
        }

        if (c + 3 < NCHUNK) { PREFETCH((c + 3) & 3, c + 3); CP_COMMIT(); }
    }

    const int g     = lane >> 2;
    const int cpair = (lane & 3) * 2;
    if (mode == 0) {
        __half* C16 = (z == 0) ? g_q16 : (z == 1) ? g_k16 : g_v16;
#pragma unroll
        for (int mt = 0; mt < 4; mt++) {
            int row0 = m0 + wm * 64 + mt * 16 + g;
#pragma unroll
            for (int nt = 0; nt < 4; nt++) {
                int col = n0 + wn * 32 + nt * 8 + cpair;
                float bx = bias[col], by = bias[col + 1];
#pragma unroll
                for (int rr = 0; rr < 2; rr++) {
                    size_t off = (size_t)(row0 + rr * 8) * DMODEL + col;
                    *(__half2*)(C16 + off) =
                        __floats2half2_rn(acc[mt][nt][rr * 2 + 0] + bx,
                                          acc[mt][nt][rr * 2 + 1] + by);
                }
            }
        }
    } else {
        float* C = outp;
#pragma unroll
        for (int mt = 0; mt < 4; mt++) {
            int row0 = m0 + wm * 64 + mt * 16 + g;
#pragma unroll
            for (int nt = 0; nt < 4; nt++) {
                int col = n0 + wn * 32 + nt * 8 + cpair;
                float bx = bias[col], by = bias[col + 1];
                *(float2*)(C + (size_t)row0 * DMODEL + col) =
                    make_float2(acc[mt][nt][0] + bx, acc[mt][nt][1] + by);
                *(float2*)(C + (size_t)(row0 + 8) * DMODEL + col) =
                    make_float2(acc[mt][nt][2] + bx, acc[mt][nt][3] + by);
            }
        }
    }
#undef PREFETCH
}

// ============================================================
// Banded flash-attention, single fp16 Q/K/V and single fp16 P.
// CTA = (128 queries, head, batch); 8 warps; warp = 16 query rows.
// smem: Q 128x72h, K 256x72h, V 256x72h = 92160 B -> 2 CTAs/SM.
// ============================================================
#define APITCHB  144
#define A_Q      0
#define A_K      18432              // 128*144
#define A_V      55296              // +256*144
#define ATTN_SMEM 92160

__global__ __launch_bounds__(256, 2) void attn_mma_kernel()
{
    extern __shared__ char sm[];
    const uint32_t sb = smem_u32(sm);

    const int tid  = threadIdx.x;
    const int lane = tid & 31;
    const int w    = tid >> 5;          // 0..7
    const int b    = blockIdx.z;
    const int h    = blockIdx.y;
    const int q0   = blockIdx.x * 128;
    const int kbase = q0 - WIN;
    const size_t tok0 = (size_t)b * SEQ;
    const int coff = h * HDIM;

    // ---- group 0: Q (128 rows) + K (256 rows); group 1: V (256 rows) ----
#pragma unroll
    for (int i = 0; i < 4; i++) {
        int task = tid + i * 256;          // 1024 tasks
        int row = task >> 3, seg = task & 7;
        uint32_t d = sb + A_Q + (uint32_t)row * APITCHB + (uint32_t)seg * 16;
        cp_async16(d, g_q16 + (tok0 + q0 + row) * DMODEL + coff + seg * 8);
    }
#pragma unroll
    for (int i = 0; i < 8; i++) {
        int task = tid + i * 256;          // 2048 tasks
        int row = task >> 3, seg = task & 7;
        int kg = kbase + row;
        int kgc = min(max(kg, 0), SEQ - 1);
        uint32_t sz = (kg >= 0 && kg < SEQ) ? 16u : 0u;
        uint32_t d = sb + A_K + (uint32_t)row * APITCHB + (uint32_t)seg * 16;
        cp_async16z(d, g_k16 + (tok0 + kgc) * DMODEL + coff + seg * 8, sz);
    }
    CP_COMMIT();
#pragma unroll
    for (int i = 0; i < 8; i++) {
        int task = tid + i * 256;
        int row = task >> 3, seg = task & 7;
        int kg = kbase + row;
        int kgc = min(max(kg, 0), SEQ - 1);
        uint32_t sz = (kg >= 0 && kg < SEQ) ? 16u : 0u;
        uint32_t d = sb + A_V + (uint32_t)row * APITCHB + (uint32_t)seg * 16;
        cp_async16z(d, g_v16 + (tok0 + kgc) * DMODEL + coff + seg * 8, sz);
    }
    CP_COMMIT();

    CP_WAIT(1);
    __syncthreads();

    // ---- Q fragments ----
    const int arow = w * 16 + ((lane >> 3) & 1) * 8 + (lane & 7);
    const int akoff = (lane >> 4) * 8;
    uint32_t qf[4][4];
#pragma unroll
    for (int kc = 0; kc < 4; kc++) {
        uint32_t ad = sb + A_Q + (uint32_t)arow * APITCHB + (uint32_t)(kc * 16 + akoff) * 2;
        ldsm_x4(qf[kc], ad);
    }

    // ---- QK: S[16][144], 18 n-tiles as 9 pairs via ldsm_x4, 1 pass ----
    float s[18][4];
#pragma unroll
    for (int t = 0; t < 18; t++)
#pragma unroll
        for (int e = 0; e < 4; e++) s[t][e] = 0.f;

    const int krow4 = (lane & 7) + ((lane >> 4) << 3);
    const int kko4  = ((lane >> 3) & 1) * 16;       // bytes
#pragma unroll
    for (int u = 0; u < 9; u++) {
        int ntb = 2 * w + 2 * u;
        uint32_t kb_addr = sb + A_K + (uint32_t)(ntb * 8 + krow4) * APITCHB + (uint32_t)kko4;
#pragma unroll
        for (int kc = 0; kc < 4; kc++) {
            uint32_t k4[4];
            ldsm_x4(k4, kb_addr + (uint32_t)kc * 32);
            uint32_t b0[2] = { k4[0], k4[1] }, b1[2] = { k4[2], k4[3] };
            mma_f16(s[2 * u],     qf[kc], b0);
            mma_f16(s[2 * u + 1], qf[kc], b1);
        }
    }

    // ---- mask + softmax ----
    const int g  = lane >> 2;
    const int c2 = (lane & 3) * 2;
    const int qg0 = q0 + w * 16 + g;
    const int qg1 = qg0 + 8;
    const float scale = 0.125f;

    float m0 = -1e30f, m1 = -1e30f;
#pragma unroll
    for (int t = 0; t < 18; t++) {
        int j0 = (2 * w + t) * 8 + c2;
        int kg0 = kbase + j0, kg1 = kg0 + 1;
        bool in0 = (kg0 >= 0) && (kg0 < SEQ);
        bool in1 = (kg1 >= 0) && (kg1 < SEQ);
        int d00 = kg0 - qg0, d10 = kg1 - qg0, d01 = kg0 - qg1, d11 = kg1 - qg1;
        s[t][0] = (in0 && d00 <= WIN && d00 >= -WIN) ? s[t][0] * scale : -1e30f;
        s[t][1] = (in1 && d10 <= WIN && d10 >= -WIN) ? s[t][1] * scale : -1e30f;
        s[t][2] = (in0 && d01 <= WIN && d01 >= -WIN) ? s[t][2] * scale : -1e30f;
        s[t][3] = (in1 && d11 <= WIN && d11 >= -WIN) ? s[t][3] * scale : -1e30f;
        m0 = fmaxf(m0, fmaxf(s[t][0], s[t][1]));
        m1 = fmaxf(m1, fmaxf(s[t][2], s[t][3]));
    }
    m0 = fmaxf(m0, __shfl_xor_sync(0xffffffffu, m0, 1));
    m0 = fmaxf(m0, __shfl_xor_sync(0xffffffffu, m0, 2));
    m1 = fmaxf(m1, __shfl_xor_sync(0xffffffffu, m1, 1));
    m1 = fmaxf(m1, __shfl_xor_sync(0xffffffffu, m1, 2));

    float r0 = 0.f, r1 = 0.f;
#pragma unroll
    for (int t = 0; t < 18; t++) {
        s[t][0] = __expf(s[t][0] - m0);
        s[t][1] = __expf(s[t][1] - m0);
        s[t][2] = __expf(s[t][2] - m1);
        s[t][3] = __expf(s[t][3] - m1);
        r0 += s[t][0] + s[t][1];
        r1 += s[t][2] + s[t][3];
    }
    r0 += __shfl_xor_sync(0xffffffffu, r0, 1);
    r0 += __shfl_xor_sync(0xffffffffu, r0, 2);
    r1 += __shfl_xor_sync(0xffffffffu, r1, 1);
    r1 += __shfl_xor_sync(0xffffffffu, r1, 2);
    float inv0 = 1.f / r0, inv1 = 1.f / r1;

    // ---- pack P into single-fp16 A-fragments ----
    uint32_t ph01[18], ph23[18];
#pragma unroll
    for (int t = 0; t < 18; t++) {
        ph01[t] = pack_hf2(s[t][0] * inv0, s[t][1] * inv0);
        ph23[t] = pack_hf2(s[t][2] * inv1, s[t][3] * inv1);
    }

    CP_WAIT(0);
    __syncthreads();

    // ---- PV: out[16][64], single pass, V single fp16 ----
    float o[8][4];
#pragma unroll
    for (int nt = 0; nt < 8; nt++)
#pragma unroll
        for (int e = 0; e < 4; e++) o[nt][e] = 0.f;

    const int vrow_l = ((lane >> 3) & 1) * 8 + (lane & 7);
#pragma unroll
    for (int jl = 0; jl < 9; jl++) {
        uint32_t ah[4] = { ph01[2 * jl], ph23[2 * jl], ph01[2 * jl + 1], ph23[2 * jl + 1] };
        int keyb = (w + jl) * 16;
        uint32_t va_base = sb + A_V + (uint32_t)(keyb + vrow_l) * APITCHB;
#pragma unroll
        for (int nt = 0; nt < 8; nt++) {
            uint32_t vf[2];
            ldsm_x2t(vf, va_base + (uint32_t)nt * 16);
            mma_f16(o[nt], ah, vf);
        }
    }

    size_t row0 = tok0 + qg0;
    size_t row1 = tok0 + qg1;
#pragma unroll
    for (int nt = 0; nt < 8; nt++) {
        int col = coff + nt * 8 + c2;
        *(__half2*)(g_a16 + row0 * DMODEL + col) = __floats2half2_rn(o[nt][0], o[nt][1]);
        *(__half2*)(g_a16 + row1 * DMODEL + col) = __floats2half2_rn(o[nt][2], o[nt][3]);
    }
}

// ============================================================
extern "C" void kernel_launch(void* const* d_in, const int* in_sizes, int n_in,
                              void* d_out, int out_size)
{
    const float* x  = (const float*)d_in[0];
    const float* Wq = (const float*)d_in[1];
    const float* bq = (const float*)d_in[2];
    const float* Wk = (const float*)d_in[3];
    const float* bk = (const float*)d_in[4];
    const float* Wv = (const float*)d_in[5];
    const float* bv = (const float*)d_in[6];
    const float* Wo = (const float*)d_in[7];
    const float* bo = (const float*)d_in[8];
    float* out = (float*)d_out;

    cudaFuncSetAttribute(hmma_gemm_kernel, cudaFuncAttributeMaxDynamicSharedMemorySize, GEMM_SMEM);
    cudaFuncSetAttribute(attn_mma_kernel, cudaFuncAttributeMaxDynamicSharedMemorySize, ATTN_SMEM);

    prep_kernel<<<MTOT + 4096, 256>>>(x, Wq, Wk, Wv, Wo);

    dim3 gq(DMODEL / 128, MTOT / 128, 3);
    hmma_gemm_kernel<<<gq, 256, GEMM_SMEM>>>(0, bq, bk, bv, nullptr);

    dim3 ga(SEQ / 128, NHEADS, BATCH);
    attn_mma_kernel<<<ga, 256, ATTN_SMEM>>>();

    dim3 go(DMODEL / 128, MTOT / 128, 1);
    hmma_gemm_kernel<<<go, 256, GEMM_SMEM>>>(1, bo, nullptr, nullptr, out);
}

// round 16
// speedup vs baseline: 1.1519x; 1.0109x over previous
#include <cuda_runtime.h>
#include <cuda_bf16.h>
#include <cuda_fp16.h>
#include <math.h>
#include <stdint.h>

#define BATCH   2
#define SEQ     2048
#define DMODEL  1024
#define NHEADS  16
#define HDIM    64
#define WIN     64
#define MTOT    (BATCH*SEQ)   // 4096
#define WSZ     (DMODEL*DMODEL)

// ---------------- scratch (static device globals) ----------------
__device__ __half g_x16[MTOT*DMODEL];          // x rounded to fp16
__device__ __half g_w16[4*WSZ];                // ORIGINAL [k][n] layout, fp16
__device__ __half g_q16[MTOT*DMODEL];
__device__ __half g_k16[MTOT*DMODEL];
__device__ __half g_v16[MTOT*DMODEL];
__device__ __half g_a16[MTOT*DMODEL];          // attention out, fp16

// ---------------- PTX helpers (non-'a' features only) ----------------
__device__ __forceinline__ uint32_t smem_u32(const void* p) {
    uint32_t a;
    asm("{ .reg .u64 t; cvta.to.shared.u64 t, %1; cvt.u32.u64 %0, t; }" : "=r"(a) : "l"(p));
    return a;
}
__device__ __forceinline__ void cp_async16(uint32_t s, const void* g) {
    asm volatile("cp.async.cg.shared.global [%0], [%1], 16;" :: "r"(s), "l"(g));
}
__device__ __forceinline__ void cp_async16z(uint32_t s, const void* g, uint32_t srcsz) {
    asm volatile("cp.async.cg.shared.global [%0], [%1], 16, %2;" :: "r"(s), "l"(g), "r"(srcsz));
}
#define CP_COMMIT() asm volatile("cp.async.commit_group;" ::: "memory")
#define CP_WAIT(n)  asm volatile("cp.async.wait_group %0;" :: "n"(n) : "memory")

__device__ __forceinline__ void ldsm_x4(uint32_t* r, uint32_t a) {
    asm volatile("ldmatrix.sync.aligned.m8n8.x4.shared.b16 {%0,%1,%2,%3}, [%4];"
        : "=r"(r[0]), "=r"(r[1]), "=r"(r[2]), "=r"(r[3]) : "r"(a));
}
__device__ __forceinline__ void ldsm_x2t(uint32_t* r, uint32_t a) {
    asm volatile("ldmatrix.sync.aligned.m8n8.x2.trans.shared.b16 {%0,%1}, [%2];"
        : "=r"(r[0]), "=r"(r[1]) : "r"(a));
}
__device__ __forceinline__ void mma_f16(float* d, const uint32_t* a, const uint32_t* b) {
    asm volatile(
        "mma.sync.aligned.m16n8k16.row.col.f32.f16.f16.f32 "
        "{%0,%1,%2,%3}, {%4,%5,%6,%7}, {%8,%9}, {%0,%1,%2,%3};"
        : "+f"(d[0]), "+f"(d[1]), "+f"(d[2]), "+f"(d[3])
        : "r"(a[0]), "r"(a[1]), "r"(a[2]), "r"(a[3]), "r"(b[0]), "r"(b[1]));
}

__device__ __forceinline__ uint32_t pack_hf2(float x, float y) {
    __half2 h = __floats2half2_rn(x, y);
    return *(uint32_t*)&h;
}

// ============================================================
// Fused prep (all streaming):
//   blocks [0,4096):      convert x -> fp16
//   blocks [4096,8192):   convert W (original [k][n] layout) -> fp16
// ============================================================
__global__ __launch_bounds__(256) void prep_kernel(
    const float* __restrict__ x,
    const float* __restrict__ Wq, const float* __restrict__ Wk,
    const float* __restrict__ Wv, const float* __restrict__ Wo)
{
    int bid = blockIdx.x;
    if (bid < MTOT) {
        size_t off = (size_t)bid * DMODEL + threadIdx.x * 4;
        float4 v = *(const float4*)(x + off);
        *(__half2*)(g_x16 + off)     = __floats2half2_rn(v.x, v.y);
        *(__half2*)(g_x16 + off + 2) = __floats2half2_rn(v.z, v.w);
    } else {
        int t = bid - MTOT;
        int z = t >> 10;
        int row = t & 1023;
        const float* W = (z == 0) ? Wq : (z == 1) ? Wk : (z == 2) ? Wv : Wo;
        size_t off = (size_t)row * DMODEL + threadIdx.x * 4;
        float4 v = *(const float4*)(W + off);
        size_t o = (size_t)z * WSZ + off;
        *(__half2*)(g_w16 + o)     = __floats2half2_rn(v.x, v.y);
        *(__half2*)(g_w16 + o + 2) = __floats2half2_rn(v.z, v.w);
    }
}

// ============================================================
// Single-pass fp16 HMMA GEMM: C = A16 @ W16 + bias, W in [k][n].
// CTA tile 128x128, BK=64, 8 warps (2x4), warp tile 64x32.
// A smem [128 m][64 k] pitch 144B; B smem [64 k][128 n] pitch 272B.
// 3-stage cp.async, ONE barrier per 64-k chunk (16 total);
// 105 KB smem -> 2 CTAs/SM.
// ============================================================
#define BK        64
#define APITCH_G  144                  // A: 128B data + 16B pad
#define MAT_A     (128*APITCH_G)       // 18432 B
#define BPITCH    272                  // B: 256B data + 16B pad
#define MAT_BB    (64*BPITCH)          // 17408 B
#define STAGE_SZ  (MAT_A + MAT_BB)     // 35840 B
#define NSTAGE    3
#define GEMM_SMEM (NSTAGE*STAGE_SZ)    // 107520 B

__global__ __launch_bounds__(256) void hmma_gemm_kernel(
    int mode, const float* __restrict__ b0, const float* __restrict__ b1,
    const float* __restrict__ b2, float* __restrict__ outp)
{
    extern __shared__ char sm[];
    const uint32_t sbase = smem_u32(sm);

    const int tid  = threadIdx.x;
    const int lane = tid & 31;
    const int wid  = tid >> 5;
    const int wm   = wid >> 2;
    const int wn   = wid & 3;
    const int m0   = blockIdx.y * 128;
    const int n0   = blockIdx.x * 128;
    const int z    = blockIdx.z;

    const __half *A, *B;
    const float* bias;
    if (mode == 0) {
        A = g_x16;
        B = g_w16 + (size_t)z * WSZ;
        bias = (z == 0) ? b0 : (z == 1) ? b1 : b2;
    } else {
        A = g_a16;
        B = g_w16 + 3ull * WSZ;
        bias = b0;
    }

    // A: 128 rows x 8 segs (16B) = 1024 tasks; B: 64 rows x 16 segs = 1024 tasks
    const int rowA = tid >> 3, segA = tid & 7;            // +i*32 rows
    const int rowB = tid >> 4, segB = tid & 15;           // +i*16 rows

#define PREFETCH(stage, cc) do {                                                 \
    const int _k0 = (cc) * BK;                                                   \
    const uint32_t _sb = sbase + (uint32_t)(stage) * STAGE_SZ;                   \
    _Pragma("unroll")                                                            \
    for (int _i = 0; _i < 4; _i++) {                                             \
        int _ra = rowA + _i * 32;                                                \
        cp_async16(_sb + (uint32_t)_ra * APITCH_G + (uint32_t)segA * 16,         \
                   A + (size_t)(m0 + _ra) * DMODEL + _k0 + segA * 8);            \
        int _rb = rowB + _i * 16;                                                \
        cp_async16(_sb + MAT_A + (uint32_t)_rb * BPITCH + (uint32_t)segB * 16,   \
                   B + (size_t)(_k0 + _rb) * DMODEL + n0 + segB * 8);            \
    }                                                                            \
} while (0)

    float acc[4][4][4];
#pragma unroll
    for (int i = 0; i < 4; i++)
#pragma unroll
        for (int j = 0; j < 4; j++)
#pragma unroll
            for (int e = 0; e < 4; e++) acc[i][j][e] = 0.f;

    const int arow_l = ((lane >> 3) & 1) * 8 + (lane & 7);
    const int akoff  = (lane >> 4) * 8;
    const int btrow  = ((lane >> 3) & 1) * 8 + (lane & 7);

    PREFETCH(0, 0); CP_COMMIT();
    PREFETCH(1, 1); CP_COMMIT();

    const int NCHUNK = DMODEL / BK;   // 16
    for (int c = 0; c < NCHUNK; c++) {
        if (c + 2 <= NCHUNK) { CP_WAIT(1); }
        else                 { CP_WAIT(0); }
        __syncthreads();

        const uint32_t stb = sbase + (uint32_t)(c % 3) * STAGE_SZ;
#pragma unroll
        for (int ks = 0; ks < 4; ks++) {
            uint32_t a[4][4], bfr[4][2];
#pragma unroll
            for (int mt = 0; mt < 4; mt++) {
                uint32_t ad = stb + (uint32_t)(wm * 64 + mt * 16 + arow_l) * APITCH_G
                                  + (uint32_t)(ks * 16 + akoff) * 2;
                ldsm_x4(a[mt], ad);
            }
#pragma unroll
            for (int nt = 0; nt < 4; nt++) {
                uint32_t bd = stb + MAT_A
                                  + (uint32_t)(ks * 16 + btrow) * BPITCH
                                  + (uint32_t)(wn * 32 + nt * 8) * 2;
                ldsm_x2t(bfr[nt], bd);
            }
#pragma unroll
            for (int mt = 0; mt < 4; mt++)
#pragma unroll
                for (int nt = 0; nt < 4; nt++)
                    mma_f16(acc[mt][nt], a[mt], bfr[nt]);
        }

        // prefetch c+2 into stage (c+2)%3 == (c-1)%3 — barrier above guarantees
        // every warp finished reading stage c-1.
        if (c + 2 < NCHUNK) { PREFETCH((c + 2) % 3, c + 2); CP_COMMIT(); }
    }

    const int g     = lane >> 2;
    const int cpair = (lane & 3) * 2;
    if (mode == 0) {
        __half* C16 = (z == 0) ? g_q16 : (z == 1) ? g_k16 : g_v16;
#pragma unroll
        for (int mt = 0; mt < 4; mt++) {
            int row0 = m0 + wm * 64 + mt * 16 + g;
#pragma unroll
            for (int nt = 0; nt < 4; nt++) {
                int col = n0 + wn * 32 + nt * 8 + cpair;
                float bx = bias[col], by = bias[col + 1];
#pragma unroll
                for (int rr = 0; rr < 2; rr++) {
                    size_t off = (size_t)(row0 + rr * 8) * DMODEL + col;
                    *(__half2*)(C16 + off) =
                        __floats2half2_rn(acc[mt][nt][rr * 2 + 0] + bx,
                                          acc[mt][nt][rr * 2 + 1] + by);
                }
            }
        }
    } else {
        float* C = outp;
#pragma unroll
        for (int mt = 0; mt < 4; mt++) {
            int row0 = m0 + wm * 64 + mt * 16 + g;
#pragma unroll
            for (int nt = 0; nt < 4; nt++) {
                int col = n0 + wn * 32 + nt * 8 + cpair;
                float bx = bias[col], by = bias[col + 1];
                *(float2*)(C + (size_t)row0 * DMODEL + col) =
                    make_float2(acc[mt][nt][0] + bx, acc[mt][nt][1] + by);
                *(float2*)(C + (size_t)(row0 + 8) * DMODEL + col) =
                    make_float2(acc[mt][nt][2] + bx, acc[mt][nt][3] + by);
            }
        }
    }
#undef PREFETCH
}

// ============================================================
// Banded flash-attention, single fp16 Q/K/V and single fp16 P.
// CTA = (128 queries, head, batch); 8 warps; warp = 16 query rows.
// smem: Q 128x72h, K 256x72h, V 256x72h = 92160 B -> 2 CTAs/SM.
// ============================================================
#define APITCHB  144
#define A_Q      0
#define A_K      18432              // 128*144
#define A_V      55296              // +256*144
#define ATTN_SMEM 92160

__global__ __launch_bounds__(256, 2) void attn_mma_kernel()
{
    extern __shared__ char sm[];
    const uint32_t sb = smem_u32(sm);

    const int tid  = threadIdx.x;
    const int lane = tid & 31;
    const int w    = tid >> 5;          // 0..7
    const int b    = blockIdx.z;
    const int h    = blockIdx.y;
    const int q0   = blockIdx.x * 128;
    const int kbase = q0 - WIN;
    const size_t tok0 = (size_t)b * SEQ;
    const int coff = h * HDIM;

    // ---- group 0: Q (128 rows) + K (256 rows); group 1: V (256 rows) ----
#pragma unroll
    for (int i = 0; i < 4; i++) {
        int task = tid + i * 256;
        int row = task >> 3, seg = task & 7;
        uint32_t d = sb + A_Q + (uint32_t)row * APITCHB + (uint32_t)seg * 16;
        cp_async16(d, g_q16 + (tok0 + q0 + row) * DMODEL + coff + seg * 8);
    }
#pragma unroll
    for (int i = 0; i < 8; i++) {
        int task = tid + i * 256;
        int row = task >> 3, seg = task & 7;
        int kg = kbase + row;
        int kgc = min(max(kg, 0), SEQ - 1);
        uint32_t sz = (kg >= 0 && kg < SEQ) ? 16u : 0u;
        uint32_t d = sb + A_K + (uint32_t)row * APITCHB + (uint32_t)seg * 16;
        cp_async16z(d, g_k16 + (tok0 + kgc) * DMODEL + coff + seg * 8, sz);
    }
    CP_COMMIT();
#pragma unroll
    for (int i = 0; i < 8; i++) {
        int task = tid + i * 256;
        int row = task >> 3, seg = task & 7;
        int kg = kbase + row;
        int kgc = min(max(kg, 0), SEQ - 1);
        uint32_t sz = (kg >= 0 && kg < SEQ) ? 16u : 0u;
        uint32_t d = sb + A_V + (uint32_t)row * APITCHB + (uint32_t)seg * 16;
        cp_async16z(d, g_v16 + (tok0 + kgc) * DMODEL + coff + seg * 8, sz);
    }
    CP_COMMIT();

    CP_WAIT(1);
    __syncthreads();

    // ---- Q fragments ----
    const int arow = w * 16 + ((lane >> 3) & 1) * 8 + (lane & 7);
    const int akoff = (lane >> 4) * 8;
    uint32_t qf[4][4];
#pragma unroll
    for (int kc = 0; kc < 4; kc++) {
        uint32_t ad = sb + A_Q + (uint32_t)arow * APITCHB + (uint32_t)(kc * 16 + akoff) * 2;
        ldsm_x4(qf[kc], ad);
    }

    // ---- QK: S[16][144], 18 n-tiles as 9 pairs via ldsm_x4, 1 pass ----
    float s[18][4];
#pragma unroll
    for (int t = 0; t < 18; t++)
#pragma unroll
        for (int e = 0; e < 4; e++) s[t][e] = 0.f;

    const int krow4 = (lane & 7) + ((lane >> 4) << 3);
    const int kko4  = ((lane >> 3) & 1) * 16;       // bytes
#pragma unroll
    for (int u = 0; u < 9; u++) {
        int ntb = 2 * w + 2 * u;
        uint32_t kb_addr = sb + A_K + (uint32_t)(ntb * 8 + krow4) * APITCHB + (uint32_t)kko4;
#pragma unroll
        for (int kc = 0; kc < 4; kc++) {
            uint32_t k4[4];
            ldsm_x4(k4, kb_addr + (uint32_t)kc * 32);
            uint32_t b0[2] = { k4[0], k4[1] }, b1[2] = { k4[2], k4[3] };
            mma_f16(s[2 * u],     qf[kc], b0);
            mma_f16(s[2 * u + 1], qf[kc], b1);
        }
    }

    // ---- mask + softmax ----
    const int g  = lane >> 2;
    const int c2 = (lane & 3) * 2;
    const int qg0 = q0 + w * 16 + g;
    const int qg1 = qg0 + 8;
    const float scale = 0.125f;

    float m0 = -1e30f, m1 = -1e30f;
#pragma unroll
    for (int t = 0; t < 18; t++) {
        int j0 = (2 * w + t) * 8 + c2;
        int kg0 = kbase + j0, kg1 = kg0 + 1;
        bool in0 = (kg0 >= 0) && (kg0 < SEQ);
        bool in1 = (kg1 >= 0) && (kg1 < SEQ);
        int d00 = kg0 - qg0, d10 = kg1 - qg0, d01 = kg0 - qg1, d11 = kg1 - qg1;
        s[t][0] = (in0 && d00 <= WIN && d00 >= -WIN) ? s[t][0] * scale : -1e30f;
        s[t][1] = (in1 && d10 <= WIN && d10 >= -WIN) ? s[t][1] * scale : -1e30f;
        s[t][2] = (in0 && d01 <= WIN && d01 >= -WIN) ? s[t][2] * scale : -1e30f;
        s[t][3] = (in1 && d11 <= WIN && d11 >= -WIN) ? s[t][3] * scale : -1e30f;
        m0 = fmaxf(m0, fmaxf(s[t][0], s[t][1]));
        m1 = fmaxf(m1, fmaxf(s[t][2], s[t][3]));
    }
    m0 = fmaxf(m0, __shfl_xor_sync(0xffffffffu, m0, 1));
    m0 = fmaxf(m0, __shfl_xor_sync(0xffffffffu, m0, 2));
    m1 = fmaxf(m1, __shfl_xor_sync(0xffffffffu, m1, 1));
    m1 = fmaxf(m1, __shfl_xor_sync(0xffffffffu, m1, 2));

    float r0 = 0.f, r1 = 0.f;
#pragma unroll
    for (int t = 0; t < 18; t++) {
        s[t][0] = __expf(s[t][0] - m0);
        s[t][1] = __expf(s[t][1] - m0);
        s[t][2] = __expf(s[t][2] - m1);
        s[t][3] = __expf(s[t][3] - m1);
        r0 += s[t][0] + s[t][1];
        r1 += s[t][2] + s[t][3];
    }
    r0 += __shfl_xor_sync(0xffffffffu, r0, 1);
    r0 += __shfl_xor_sync(0xffffffffu, r0, 2);
    r1 += __shfl_xor_sync(0xffffffffu, r1, 1);
    r1 += __shfl_xor_sync(0xffffffffu, r1, 2);
    float inv0 = 1.f / r0, inv1 = 1.f / r1;

    // ---- pack P into single-fp16 A-fragments ----
    uint32_t ph01[18], ph23[18];
#pragma unroll
    for (int t = 0; t < 18; t++) {
        ph01[t] = pack_hf2(s[t][0] * inv0, s[t][1] * inv0);
        ph23[t] = pack_hf2(s[t][2] * inv1, s[t][3] * inv1);
    }

    CP_WAIT(0);
    __syncthreads();

    // ---- PV: out[16][64], single pass, V single fp16 ----
    float o[8][4];
#pragma unroll
    for (int nt = 0; nt < 8; nt++)
#pragma unroll
        for (int e = 0; e < 4; e++) o[nt][e] = 0.f;

    const int vrow_l = ((lane >> 3) & 1) * 8 + (lane & 7);
#pragma unroll
    for (int jl = 0; jl < 9; jl++) {
        uint32_t ah[4] = { ph01[2 * jl], ph23[2 * jl], ph01[2 * jl + 1], ph23[2 * jl + 1] };
        int keyb = (w + jl) * 16;
        uint32_t va_base = sb + A_V + (uint32_t)(keyb + vrow_l) * APITCHB;
#pragma unroll
        for (int nt = 0; nt < 8; nt++) {
            uint32_t vf[2];
            ldsm_x2t(vf, va_base + (uint32_t)nt * 16);
            mma_f16(o[nt], ah, vf);
        }
    }

    size_t row0 = tok0 + qg0;
    size_t row1 = tok0 + qg1;
#pragma unroll
    for (int nt = 0; nt < 8; nt++) {
        int col = coff + nt * 8 + c2;
        *(__half2*)(g_a16 + row0 * DMODEL + col) = __floats2half2_rn(o[nt][0], o[nt][1]);
        *(__half2*)(g_a16 + row1 * DMODEL + col) = __floats2half2_rn(o[nt][2], o[nt][3]);
    }
}

// ============================================================
extern "C" void kernel_launch(void* const* d_in, const int* in_sizes, int n_in,
                              void* d_out, int out_size)
{
    const float* x  = (const float*)d_in[0];
    const float* Wq = (const float*)d_in[1];
    const float* bq = (const float*)d_in[2];
    const float* Wk = (const float*)d_in[3];
    const float* bk = (const float*)d_in[4];
    const float* Wv = (const float*)d_in[5];
    const float* bv = (const float*)d_in[6];
    const float* Wo = (const float*)d_in[7];
    const float* bo = (const float*)d_in[8];
    float* out = (float*)d_out;

    cudaFuncSetAttribute(hmma_gemm_kernel, cudaFuncAttributeMaxDynamicSharedMemorySize, GEMM_SMEM);
    cudaFuncSetAttribute(attn_mma_kernel, cudaFuncAttributeMaxDynamicSharedMemorySize, ATTN_SMEM);

    prep_kernel<<<MTOT + 4096, 256>>>(x, Wq, Wk, Wv, Wo);

    dim3 gq(DMODEL / 128, MTOT / 128, 3);
    hmma_gemm_kernel<<<gq, 256, GEMM_SMEM>>>(0, bq, bk, bv, nullptr);

    dim3 ga(SEQ / 128, NHEADS, BATCH);
    attn_mma_kernel<<<ga, 256, ATTN_SMEM>>>();

    dim3 go(DMODEL / 128, MTOT / 128, 1);
    hmma_gemm_kernel<<<go, 256, GEMM_SMEM>>>(1, bo, nullptr, nullptr, out);
}

// round 17
// speedup vs baseline: 1.1580x; 1.0053x over previous
#include <cuda_runtime.h>
#include <cuda_bf16.h>
#include <cuda_fp16.h>
#include <math.h>
#include <stdint.h>

#define BATCH   2
#define SEQ     2048
#define DMODEL  1024
#define NHEADS  16
#define HDIM    64
#define WIN     64
#define MTOT    (BATCH*SEQ)   // 4096
#define WSZ     (DMODEL*DMODEL)

// ---------------- scratch (static device globals) ----------------
__device__ __half g_x16[MTOT*DMODEL];          // x rounded to fp16
__device__ __half g_w16[4*WSZ];                // ORIGINAL [k][n] layout, fp16
__device__ __half g_q16[MTOT*DMODEL];
__device__ __half g_k16[MTOT*DMODEL];
__device__ __half g_v16[MTOT*DMODEL];
__device__ __half g_a16[MTOT*DMODEL];          // attention out, fp16

// ---------------- PTX helpers (non-'a' features only) ----------------
__device__ __forceinline__ uint32_t smem_u32(const void* p) {
    uint32_t a;
    asm("{ .reg .u64 t; cvta.to.shared.u64 t, %1; cvt.u32.u64 %0, t; }" : "=r"(a) : "l"(p));
    return a;
}
__device__ __forceinline__ void cp_async16(uint32_t s, const void* g) {
    asm volatile("cp.async.cg.shared.global [%0], [%1], 16;" :: "r"(s), "l"(g));
}
__device__ __forceinline__ void cp_async16z(uint32_t s, const void* g, uint32_t srcsz) {
    asm volatile("cp.async.cg.shared.global [%0], [%1], 16, %2;" :: "r"(s), "l"(g), "r"(srcsz));
}
#define CP_COMMIT() asm volatile("cp.async.commit_group;" ::: "memory")
#define CP_WAIT(n)  asm volatile("cp.async.wait_group %0;" :: "n"(n) : "memory")

__device__ __forceinline__ void ldsm_x4(uint32_t* r, uint32_t a) {
    asm volatile("ldmatrix.sync.aligned.m8n8.x4.shared.b16 {%0,%1,%2,%3}, [%4];"
        : "=r"(r[0]), "=r"(r[1]), "=r"(r[2]), "=r"(r[3]) : "r"(a));
}
__device__ __forceinline__ void ldsm_x4t(uint32_t* r, uint32_t a) {
    asm volatile("ldmatrix.sync.aligned.m8n8.x4.trans.shared.b16 {%0,%1,%2,%3}, [%4];"
        : "=r"(r[0]), "=r"(r[1]), "=r"(r[2]), "=r"(r[3]) : "r"(a));
}
__device__ __forceinline__ void ldsm_x2t(uint32_t* r, uint32_t a) {
    asm volatile("ldmatrix.sync.aligned.m8n8.x2.trans.shared.b16 {%0,%1}, [%2];"
        : "=r"(r[0]), "=r"(r[1]) : "r"(a));
}
__device__ __forceinline__ void mma_f16(float* d, const uint32_t* a, const uint32_t* b) {
    asm volatile(
        "mma.sync.aligned.m16n8k16.row.col.f32.f16.f16.f32 "
        "{%0,%1,%2,%3}, {%4,%5,%6,%7}, {%8,%9}, {%0,%1,%2,%3};"
        : "+f"(d[0]), "+f"(d[1]), "+f"(d[2]), "+f"(d[3])
        : "r"(a[0]), "r"(a[1]), "r"(a[2]), "r"(a[3]), "r"(b[0]), "r"(b[1]));
}

__device__ __forceinline__ uint32_t pack_hf2(float x, float y) {
    __half2 h = __floats2half2_rn(x, y);
    return *(uint32_t*)&h;
}

// ============================================================
// Fused prep (all streaming):
//   blocks [0,4096):      convert x -> fp16
//   blocks [4096,8192):   convert W (original [k][n] layout) -> fp16
// ============================================================
__global__ __launch_bounds__(256) void prep_kernel(
    const float* __restrict__ x,
    const float* __restrict__ Wq, const float* __restrict__ Wk,
    const float* __restrict__ Wv, const float* __restrict__ Wo)
{
    int bid = blockIdx.x;
    if (bid < MTOT) {
        size_t off = (size_t)bid * DMODEL + threadIdx.x * 4;
        float4 v = *(const float4*)(x + off);
        *(__half2*)(g_x16 + off)     = __floats2half2_rn(v.x, v.y);
        *(__half2*)(g_x16 + off + 2) = __floats2half2_rn(v.z, v.w);
    } else {
        int t = bid - MTOT;
        int z = t >> 10;
        int row = t & 1023;
        const float* W = (z == 0) ? Wq : (z == 1) ? Wk : (z == 2) ? Wv : Wo;
        size_t off = (size_t)row * DMODEL + threadIdx.x * 4;
        float4 v = *(const float4*)(W + off);
        size_t o = (size_t)z * WSZ + off;
        *(__half2*)(g_w16 + o)     = __floats2half2_rn(v.x, v.y);
        *(__half2*)(g_w16 + o + 2) = __floats2half2_rn(v.z, v.w);
    }
}

// ============================================================
// Single-pass fp16 HMMA GEMM: C = A16 @ W16 + bias, W in [k][n].
// CTA tile 128x128, BK=64, 8 warps (2x4), warp tile 64x32.
// A smem [128 m][64 k] pitch 144B; B smem [64 k][128 n] pitch 272B.
// B fragments via ldmatrix.x4.trans (2 per ks instead of 4 x2t).
// 3-stage cp.async, one barrier per chunk; 105 KB -> 2 CTAs/SM.
// ============================================================
#define BK        64
#define APITCH_G  144                  // A: 128B data + 16B pad
#define MAT_A     (128*APITCH_G)       // 18432 B
#define BPITCH    272                  // B: 256B data + 16B pad
#define MAT_BB    (64*BPITCH)          // 17408 B
#define STAGE_SZ  (MAT_A + MAT_BB)     // 35840 B
#define NSTAGE    3
#define GEMM_SMEM (NSTAGE*STAGE_SZ)    // 107520 B

__global__ __launch_bounds__(256) void hmma_gemm_kernel(
    int mode, const float* __restrict__ b0, const float* __restrict__ b1,
    const float* __restrict__ b2, float* __restrict__ outp)
{
    extern __shared__ char sm[];
    const uint32_t sbase = smem_u32(sm);

    const int tid  = threadIdx.x;
    const int lane = tid & 31;
    const int wid  = tid >> 5;
    const int wm   = wid >> 2;
    const int wn   = wid & 3;
    const int m0   = blockIdx.y * 128;
    const int n0   = blockIdx.x * 128;
    const int z    = blockIdx.z;

    const __half *A, *B;
    const float* bias;
    if (mode == 0) {
        A = g_x16;
        B = g_w16 + (size_t)z * WSZ;
        bias = (z == 0) ? b0 : (z == 1) ? b1 : b2;
    } else {
        A = g_a16;
        B = g_w16 + 3ull * WSZ;
        bias = b0;
    }

    const int rowA = tid >> 3, segA = tid & 7;
    const int rowB = tid >> 4, segB = tid & 15;

#define PREFETCH(stage, cc) do {                                                 \
    const int _k0 = (cc) * BK;                                                   \
    const uint32_t _sb = sbase + (uint32_t)(stage) * STAGE_SZ;                   \
    _Pragma("unroll")                                                            \
    for (int _i = 0; _i < 4; _i++) {                                             \
        int _ra = rowA + _i * 32;                                                \
        cp_async16(_sb + (uint32_t)_ra * APITCH_G + (uint32_t)segA * 16,         \
                   A + (size_t)(m0 + _ra) * DMODEL + _k0 + segA * 8);            \
        int _rb = rowB + _i * 16;                                                \
        cp_async16(_sb + MAT_A + (uint32_t)_rb * BPITCH + (uint32_t)segB * 16,   \
                   B + (size_t)(_k0 + _rb) * DMODEL + n0 + segB * 8);            \
    }                                                                            \
} while (0)

    float acc[4][4][4];
#pragma unroll
    for (int i = 0; i < 4; i++)
#pragma unroll
        for (int j = 0; j < 4; j++)
#pragma unroll
            for (int e = 0; e < 4; e++) acc[i][j][e] = 0.f;

    const int arow_l = ((lane >> 3) & 1) * 8 + (lane & 7);
    const int akoff  = (lane >> 4) * 8;
    // x4t lane mapping: k-row from lanes' low 4 bits (two k-halves),
    // n offset +8 for lanes 16-31 (matrices 2,3).
    const int btr4 = ((lane >> 3) & 1) * 8 + (lane & 7);   // k row within 16
    const int btn4 = (lane >> 4) * 8;                      // n offset within pair

    PREFETCH(0, 0); CP_COMMIT();
    PREFETCH(1, 1); CP_COMMIT();

    const int NCHUNK = DMODEL / BK;   // 16
    for (int c = 0; c < NCHUNK; c++) {
        if (c + 2 <= NCHUNK) { CP_WAIT(1); }
        else                 { CP_WAIT(0); }
        __syncthreads();

        const uint32_t stb = sbase + (uint32_t)(c % 3) * STAGE_SZ;
#pragma unroll
        for (int ks = 0; ks < 4; ks++) {
            uint32_t a[4][4], bfr[4][2];
#pragma unroll
            for (int mt = 0; mt < 4; mt++) {
                uint32_t ad = stb + (uint32_t)(wm * 64 + mt * 16 + arow_l) * APITCH_G
                                  + (uint32_t)(ks * 16 + akoff) * 2;
                ldsm_x4(a[mt], ad);
            }
#pragma unroll
            for (int pair = 0; pair < 2; pair++) {
                uint32_t q4[4];
                uint32_t bd = stb + MAT_A
                                  + (uint32_t)(ks * 16 + btr4) * BPITCH
                                  + (uint32_t)(wn * 32 + pair * 16 + btn4) * 2;
                ldsm_x4t(q4, bd);
                bfr[pair * 2 + 0][0] = q4[0]; bfr[pair * 2 + 0][1] = q4[1];
                bfr[pair * 2 + 1][0] = q4[2]; bfr[pair * 2 + 1][1] = q4[3];
            }
#pragma unroll
            for (int mt = 0; mt < 4; mt++)
#pragma unroll
                for (int nt = 0; nt < 4; nt++)
                    mma_f16(acc[mt][nt], a[mt], bfr[nt]);
        }

        if (c + 2 < NCHUNK) { PREFETCH((c + 2) % 3, c + 2); CP_COMMIT(); }
    }

    const int g     = lane >> 2;
    const int cpair = (lane & 3) * 2;
    if (mode == 0) {
        __half* C16 = (z == 0) ? g_q16 : (z == 1) ? g_k16 : g_v16;
#pragma unroll
        for (int mt = 0; mt < 4; mt++) {
            int row0 = m0 + wm * 64 + mt * 16 + g;
#pragma unroll
            for (int nt = 0; nt < 4; nt++) {
                int col = n0 + wn * 32 + nt * 8 + cpair;
                float bx = bias[col], by = bias[col + 1];
#pragma unroll
                for (int rr = 0; rr < 2; rr++) {
                    size_t off = (size_t)(row0 + rr * 8) * DMODEL + col;
                    *(__half2*)(C16 + off) =
                        __floats2half2_rn(acc[mt][nt][rr * 2 + 0] + bx,
                                          acc[mt][nt][rr * 2 + 1] + by);
                }
            }
        }
    } else {
        float* C = outp;
#pragma unroll
        for (int mt = 0; mt < 4; mt++) {
            int row0 = m0 + wm * 64 + mt * 16 + g;
#pragma unroll
            for (int nt = 0; nt < 4; nt++) {
                int col = n0 + wn * 32 + nt * 8 + cpair;
                float bx = bias[col], by = bias[col + 1];
                *(float2*)(C + (size_t)row0 * DMODEL + col) =
                    make_float2(acc[mt][nt][0] + bx, acc[mt][nt][1] + by);
                *(float2*)(C + (size_t)(row0 + 8) * DMODEL + col) =
                    make_float2(acc[mt][nt][2] + bx, acc[mt][nt][3] + by);
            }
        }
    }
#undef PREFETCH
}

// ============================================================
// Banded flash-attention, single fp16 Q/K/V and single fp16 P.
// CTA = (128 queries, head, batch); 8 warps; warp = 16 query rows.
// smem: Q 128x72h, K 256x72h, V 256x72h = 92160 B -> 2 CTAs/SM.
// ============================================================
#define APITCHB  144
#define A_Q      0
#define A_K      18432              // 128*144
#define A_V      55296              // +256*144
#define ATTN_SMEM 92160

__global__ __launch_bounds__(256, 2) void attn_mma_kernel()
{
    extern __shared__ char sm[];
    const uint32_t sb = smem_u32(sm);

    const int tid  = threadIdx.x;
    const int lane = tid & 31;
    const int w    = tid >> 5;          // 0..7
    const int b    = blockIdx.z;
    const int h    = blockIdx.y;
    const int q0   = blockIdx.x * 128;
    const int kbase = q0 - WIN;
    const size_t tok0 = (size_t)b * SEQ;
    const int coff = h * HDIM;

    // ---- group 0: Q (128 rows) + K (256 rows); group 1: V (256 rows) ----
#pragma unroll
    for (int i = 0; i < 4; i++) {
        int task = tid + i * 256;
        int row = task >> 3, seg = task & 7;
        uint32_t d = sb + A_Q + (uint32_t)row * APITCHB + (uint32_t)seg * 16;
        cp_async16(d, g_q16 + (tok0 + q0 + row) * DMODEL + coff + seg * 8);
    }
#pragma unroll
    for (int i = 0; i < 8; i++) {
        int task = tid + i * 256;
        int row = task >> 3, seg = task & 7;
        int kg = kbase + row;
        int kgc = min(max(kg, 0), SEQ - 1);
        uint32_t sz = (kg >= 0 && kg < SEQ) ? 16u : 0u;
        uint32_t d = sb + A_K + (uint32_t)row * APITCHB + (uint32_t)seg * 16;
        cp_async16z(d, g_k16 + (tok0 + kgc) * DMODEL + coff + seg * 8, sz);
    }
    CP_COMMIT();
#pragma unroll
    for (int i = 0; i < 8; i++) {
        int task = tid + i * 256;
        int row = task >> 3, seg = task & 7;
        int kg = kbase + row;
        int kgc = min(max(kg, 0), SEQ - 1);
        uint32_t sz = (kg >= 0 && kg < SEQ) ? 16u : 0u;
        uint32_t d = sb + A_V + (uint32_t)row * APITCHB + (uint32_t)seg * 16;
        cp_async16z(d, g_v16 + (tok0 + kgc) * DMODEL + coff + seg * 8, sz);
    }
    CP_COMMIT();

    CP_WAIT(1);
    __syncthreads();

    // ---- Q fragments ----
    const int arow = w * 16 + ((lane >> 3) & 1) * 8 + (lane & 7);
    const int akoff = (lane >> 4) * 8;
    uint32_t qf[4][4];
#pragma unroll
    for (int kc = 0; kc < 4; kc++) {
        uint32_t ad = sb + A_Q + (uint32_t)arow * APITCHB + (uint32_t)(kc * 16 + akoff) * 2;
        ldsm_x4(qf[kc], ad);
    }

    // ---- QK: S[16][144], 18 n-tiles as 9 pairs via ldsm_x4, 1 pass ----
    float s[18][4];
#pragma unroll
    for (int t = 0; t < 18; t++)
#pragma unroll
        for (int e = 0; e < 4; e++) s[t][e] = 0.f;

    const int krow4 = (lane & 7) + ((lane >> 4) << 3);
    const int kko4  = ((lane >> 3) & 1) * 16;       // bytes
#pragma unroll
    for (int u = 0; u < 9; u++) {
        int ntb = 2 * w + 2 * u;
        uint32_t kb_addr = sb + A_K + (uint32_t)(ntb * 8 + krow4) * APITCHB + (uint32_t)kko4;
#pragma unroll
        for (int kc = 0; kc < 4; kc++) {
            uint32_t k4[4];
            ldsm_x4(k4, kb_addr + (uint32_t)kc * 32);
            uint32_t b0[2] = { k4[0], k4[1] }, b1[2] = { k4[2], k4[3] };
            mma_f16(s[2 * u],     qf[kc], b0);
            mma_f16(s[2 * u + 1], qf[kc], b1);
        }
    }

    // ---- mask + softmax ----
    const int g  = lane >> 2;
    const int c2 = (lane & 3) * 2;
    const int qg0 = q0 + w * 16 + g;
    const int qg1 = qg0 + 8;
    const float scale = 0.125f;

    float m0 = -1e30f, m1 = -1e30f;
#pragma unroll
    for (int t = 0; t < 18; t++) {
        int j0 = (2 * w + t) * 8 + c2;
        int kg0 = kbase + j0, kg1 = kg0 + 1;
        bool in0 = (kg0 >= 0) && (kg0 < SEQ);
        bool in1 = (kg1 >= 0) && (kg1 < SEQ);
        int d00 = kg0 - qg0, d10 = kg1 - qg0, d01 = kg0 - qg1, d11 = kg1 - qg1;
        s[t][0] = (in0 && d00 <= WIN && d00 >= -WIN) ? s[t][0] * scale : -1e30f;
        s[t][1] = (in1 && d10 <= WIN && d10 >= -WIN) ? s[t][1] * scale : -1e30f;
        s[t][2] = (in0 && d01 <= WIN && d01 >= -WIN) ? s[t][2] * scale : -1e30f;
        s[t][3] = (in1 && d11 <= WIN && d11 >= -WIN) ? s[t][3] * scale : -1e30f;
        m0 = fmaxf(m0, fmaxf(s[t][0], s[t][1]));
        m1 = fmaxf(m1, fmaxf(s[t][2], s[t][3]));
    }
    m0 = fmaxf(m0, __shfl_xor_sync(0xffffffffu, m0, 1));
    m0 = fmaxf(m0, __shfl_xor_sync(0xffffffffu, m0, 2));
    m1 = fmaxf(m1, __shfl_xor_sync(0xffffffffu, m1, 1));
    m1 = fmaxf(m1, __shfl_xor_sync(0xffffffffu, m1, 2));

    float r0 = 0.f, r1 = 0.f;
#pragma unroll
    for (int t = 0; t < 18; t++) {
        s[t][0] = __expf(s[t][0] - m0);
        s[t][1] = __expf(s[t][1] - m0);
        s[t][2] = __expf(s[t][2] - m1);
        s[t][3] = __expf(s[t][3] - m1);
        r0 += s[t][0] + s[t][1];
        r1 += s[t][2] + s[t][3];
    }
    r0 += __shfl_xor_sync(0xffffffffu, r0, 1);
    r0 += __shfl_xor_sync(0xffffffffu, r0, 2);
    r1 += __shfl_xor_sync(0xffffffffu, r1, 1);
    r1 += __shfl_xor_sync(0xffffffffu, r1, 2);
    float inv0 = 1.f / r0, inv1 = 1.f / r1;

    // ---- pack P into single-fp16 A-fragments ----
    uint32_t ph01[18], ph23[18];
#pragma unroll
    for (int t = 0; t < 18; t++) {
        ph01[t] = pack_hf2(s[t][0] * inv0, s[t][1] * inv0);
        ph23[t] = pack_hf2(s[t][2] * inv1, s[t][3] * inv1);
    }

    CP_WAIT(0);
    __syncthreads();

    // ---- PV: out[16][64], single pass, V single fp16 ----
    float o[8][4];
#pragma unroll
    for (int nt = 0; nt < 8; nt++)
#pragma unroll
        for (int e = 0; e < 4; e++) o[nt][e] = 0.f;

    const int vrow_l = ((lane >> 3) & 1) * 8 + (lane & 7);
#pragma unroll
    for (int jl = 0; jl < 9; jl++) {
        uint32_t ah[4] = { ph01[2 * jl], ph23[2 * jl], ph01[2 * jl + 1], ph23[2 * jl + 1] };
        int keyb = (w + jl) * 16;
        uint32_t va_base = sb + A_V + (uint32_t)(keyb + vrow_l) * APITCHB;
#pragma unroll
        for (int nt = 0; nt < 8; nt++) {
            uint32_t vf[2];
            ldsm_x2t(vf, va_base + (uint32_t)nt * 16);
            mma_f16(o[nt], ah, vf);
        }
    }

    size_t row0 = tok0 + qg0;
    size_t row1 = tok0 + qg1;
#pragma unroll
    for (int nt = 0; nt < 8; nt++) {
        int col = coff + nt * 8 + c2;
        *(__half2*)(g_a16 + row0 * DMODEL + col) = __floats2half2_rn(o[nt][0], o[nt][1]);
        *(__half2*)(g_a16 + row1 * DMODEL + col) = __floats2half2_rn(o[nt][2], o[nt][3]);
    }
}

// ============================================================
extern "C" void kernel_launch(void* const* d_in, const int* in_sizes, int n_in,
                              void* d_out, int out_size)
{
    const float* x  = (const float*)d_in[0];
    const float* Wq = (const float*)d_in[1];
    const float* bq = (const float*)d_in[2];
    const float* Wk = (const float*)d_in[3];
    const float* bk = (const float*)d_in[4];
    const float* Wv = (const float*)d_in[5];
    const float* bv = (const float*)d_in[6];
    const float* Wo = (const float*)d_in[7];
    const float* bo = (const float*)d_in[8];
    float* out = (float*)d_out;

    cudaFuncSetAttribute(hmma_gemm_kernel, cudaFuncAttributeMaxDynamicSharedMemorySize, GEMM_SMEM);
    cudaFuncSetAttribute(attn_mma_kernel, cudaFuncAttributeMaxDynamicSharedMemorySize, ATTN_SMEM);

    prep_kernel<<<MTOT + 4096, 256>>>(x, Wq, Wk, Wv, Wo);

    dim3 gq(DMODEL / 128, MTOT / 128, 3);
    hmma_gemm_kernel<<<gq, 256, GEMM_SMEM>>>(0, bq, bk, bv, nullptr);

    dim3 ga(SEQ / 128, NHEADS, BATCH);
    attn_mma_kernel<<<ga, 256, ATTN_SMEM>>>();

    dim3 go(DMODEL / 128, MTOT / 128, 1);
    hmma_gemm_kernel<<<go, 256, GEMM_SMEM>>>(1, bo, nullptr, nullptr, out);
}